// round 13
// baseline (speedup 1.0000x reference)
#include <cuda_runtime.h>
#include <cuda_bf16.h>
#include <cstdint>

// ---------------------------------------------------------------------------
// Problem constants: B=32, N=196, DQ=256, DC=1024, H=4, DH=64, DHC=256, 4N=784
// ---------------------------------------------------------------------------

#define SZ_BNDC   6422528LL   // 32*196*1024  (also 32*784*256)
#define SZ_SC     4917248LL   // 32*4*196*196
#define SZ_Q      1605632LL   // 32*196*256
#define SZ_ATTN  19668992LL   // 32*4*196*784 (one branch)

// Scratch (device .bss, allocation-free) — same layout as round 12 except
// g_rowmax holds all 4 branches (512*196) now.
__device__ float g_q3[SZ_BNDC];
__device__ float g_k3[SZ_BNDC];
__device__ float g_v3[SZ_BNDC];
__device__ float g_sc[SZ_SC];
__device__ float g_oat[SZ_BNDC];
__device__ float g_that[SZ_BNDC];
__device__ float g_kvs[SZ_BNDC];
__device__ float g_Kb[SZ_BNDC];
__device__ float g_Vb[SZ_BNDC];
__device__ float g_Qb[SZ_Q];
__device__ float g_attn[SZ_ATTN];
__device__ float g_ctx[SZ_Q];        // stats sum/sumsq accumulators (1024 used)
__device__ float g_gain[128];
__device__ float g_rowmax[512 * 196];
__device__ float g_WkT[614656];       // 784*784
__device__ float g_WvT[614656];
__device__ float g_WqT[4 * 38416];    // 4 * 196*196

// ---------------------------------------------------------------------------
// PTX helpers
// ---------------------------------------------------------------------------
__device__ __forceinline__ uint32_t smem_u32(const void* p) {
    return (uint32_t)__cvta_generic_to_shared(p);
}

__device__ __forceinline__ void ldsm_x4(uint32_t& r0, uint32_t& r1,
                                        uint32_t& r2, uint32_t& r3, uint32_t addr) {
    asm volatile("ldmatrix.sync.aligned.m8n8.x4.shared.b16 {%0,%1,%2,%3},[%4];"
                 : "=r"(r0), "=r"(r1), "=r"(r2), "=r"(r3) : "r"(addr));
}

__device__ __forceinline__ void ldsm_x4_t(uint32_t& r0, uint32_t& r1,
                                          uint32_t& r2, uint32_t& r3, uint32_t addr) {
    asm volatile("ldmatrix.sync.aligned.m8n8.x4.trans.shared.b16 {%0,%1,%2,%3},[%4];"
                 : "=r"(r0), "=r"(r1), "=r"(r2), "=r"(r3) : "r"(addr));
}

__device__ __forceinline__ void mma_bf16(float* c, const uint32_t* a, const uint32_t* b) {
    asm volatile("mma.sync.aligned.m16n8k16.row.col.f32.bf16.bf16.f32 "
                 "{%0,%1,%2,%3},{%4,%5,%6,%7},{%8,%9},{%0,%1,%2,%3};"
                 : "+f"(c[0]), "+f"(c[1]), "+f"(c[2]), "+f"(c[3])
                 : "r"(a[0]), "r"(a[1]), "r"(a[2]), "r"(a[3]),
                   "r"(b[0]), "r"(b[1]));
}

__device__ __forceinline__ void atomicMaxF(float* a, float v) {
    int old = __float_as_int(*a);
    while (__int_as_float(old) < v) {
        int assumed = old;
        old = atomicCAS((int*)a, assumed, __float_as_int(v));
        if (old == assumed) break;
    }
}

// Split-convert 4 consecutive fp32 into hi/lo bf16 planes with ONE 8-byte
// store per plane (addresses are 8B-aligned: row strides 24/136/72 bf16).
__device__ __forceinline__ void cvt_store4(__nv_bfloat16* hi, __nv_bfloat16* lo,
                                           float4 v) {
    __nv_bfloat16 h0 = __float2bfloat16(v.x), h1 = __float2bfloat16(v.y);
    __nv_bfloat16 h2 = __float2bfloat16(v.z), h3 = __float2bfloat16(v.w);
    __nv_bfloat162 hA = __halves2bfloat162(h0, h1);
    __nv_bfloat162 hB = __halves2bfloat162(h2, h3);
    uint2 hp; hp.x = *(uint32_t*)&hA; hp.y = *(uint32_t*)&hB;
    *(uint2*)hi = hp;
    __nv_bfloat162 lA = __halves2bfloat162(
        __float2bfloat16(v.x - __bfloat162float(h0)),
        __float2bfloat16(v.y - __bfloat162float(h1)));
    __nv_bfloat162 lB = __halves2bfloat162(
        __float2bfloat16(v.z - __bfloat162float(h2)),
        __float2bfloat16(v.w - __bfloat162float(h3)));
    uint2 lp; lp.x = *(uint32_t*)&lA; lp.y = *(uint32_t*)&lB;
    *(uint2*)lo = lp;
}

// ---------------------------------------------------------------------------
// Tile geometry: 128x128 block tile, TBK=16, double-buffered STATIC smem.
// ---------------------------------------------------------------------------
#define TBM 128
#define TBN 128
#define TBK 16
#define A_STRIDE 24                 // TBK + 8 pad
#define B_STRIDE 136                // TBN + 8 pad
#define PVB_STRIDE 72               // 64 + 8 pad

// ---------------------------------------------------------------------------
// Tensor-core batched GEMM, split-bf16 (3 MMA) fp32 emulation.
// Optional fused stats epilogue (rm_st != nullptr): per-row atomic max and
// per-z atomic sum/sumsq of the (masked) outputs.
// ---------------------------------------------------------------------------
template<bool TB>
__global__ __launch_bounds__(256)
void gemm_mma(const float* __restrict__ A, const float* __restrict__ B,
              float* __restrict__ C,
              int M, int N, int K, int lda, int ldb, int ldc,
              long long sAb, long long sAh, long long sBb, long long sBh,
              long long sCb, long long sCh, int nh, float alpha,
              float* rm_st, float* sum_st)
{
    int z  = blockIdx.z;
    int bb = z / nh, hh = z % nh;
    A += bb * sAb + hh * sAh;
    B += bb * sBb + hh * sBh;
    C += bb * sCb + hh * sCh;

    __shared__ __align__(16) __nv_bfloat16 As[2][2][TBM][A_STRIDE];  // 24.0 KB
    __shared__ __align__(16) __nv_bfloat16 Bs[2][2][TBK][B_STRIDE];  // 17.0 KB

    const int tid  = threadIdx.x;
    const int lane = tid & 31;
    const int wid  = tid >> 5;
    const int wm   = wid >> 2;
    const int wn   = wid & 3;
    const int m0 = blockIdx.y * TBM, n0 = blockIdx.x * TBN;

    float acc[4][4][4];
#pragma unroll
    for (int i = 0; i < 4; i++)
#pragma unroll
        for (int j = 0; j < 4; j++)
#pragma unroll
            for (int r = 0; r < 4; r++) acc[i][j][r] = 0.f;

    const int ar  = tid >> 2, ac4 = tid & 3;    // A: 64 rows/pass, 4 f4/row
    const int bkr = tid >> 5, bc4 = tid & 31;   // B NN: 8 k-rows/pass, 32 f4/row
    const int bnr = tid >> 2, bk4 = tid & 3;    // B NT: 64 n-rows/pass, 4 f4/row

    float4 aPre[2], bPre[2];

#define LOAD_REGS(K0)                                                           \
    {                                                                           \
        int k0_ = (K0);                                                         \
        _Pragma("unroll")                                                       \
        for (int i = 0; i < 2; i++) {                                           \
            int gm = m0 + ar + i * 64, gk = k0_ + ac4 * 4;                      \
            aPre[i] = (gm < M && gk < K)                                        \
                ? *(const float4*)&A[(long long)gm * lda + gk]                  \
                : make_float4(0.f, 0.f, 0.f, 0.f);                              \
        }                                                                       \
        if (!TB) {                                                              \
            _Pragma("unroll")                                                   \
            for (int i = 0; i < 2; i++) {                                       \
                int gk = k0_ + bkr + i * 8, gn = n0 + bc4 * 4;                  \
                bPre[i] = (gk < K && gn < N)                                    \
                    ? *(const float4*)&B[(long long)gk * ldb + gn]              \
                    : make_float4(0.f, 0.f, 0.f, 0.f);                          \
            }                                                                   \
        } else {                                                                \
            _Pragma("unroll")                                                   \
            for (int i = 0; i < 2; i++) {                                       \
                int gn = n0 + bnr + i * 64, gk = k0_ + bk4 * 4;                 \
                bPre[i] = (gn < N && gk < K)                                    \
                    ? *(const float4*)&B[(long long)gn * ldb + gk]              \
                    : make_float4(0.f, 0.f, 0.f, 0.f);                          \
            }                                                                   \
        }                                                                       \
    }

#define CVT_B_SC(s, dr, dc, f)                                                  \
    {                                                                           \
        __nv_bfloat16 hi_ = __float2bfloat16(f);                                \
        Bs[s][0][dr][dc] = hi_;                                                 \
        Bs[s][1][dr][dc] = __float2bfloat16((f) - __bfloat162float(hi_));       \
    }

#define STORE_SMEM(s)                                                           \
    {                                                                           \
        _Pragma("unroll")                                                       \
        for (int i = 0; i < 2; i++) {                                           \
            int m = ar + i * 64, c = ac4 * 4;                                   \
            cvt_store4(&As[s][0][m][c], &As[s][1][m][c], aPre[i]);              \
        }                                                                       \
        if (!TB) {                                                              \
            _Pragma("unroll")                                                   \
            for (int i = 0; i < 2; i++) {                                       \
                int k = bkr + i * 8, c = bc4 * 4;                               \
                cvt_store4(&Bs[s][0][k][c], &Bs[s][1][k][c], bPre[i]);          \
            }                                                                   \
        } else {                                                                \
            _Pragma("unroll")                                                   \
            for (int i = 0; i < 2; i++) {                                       \
                int n = bnr + i * 64, k = bk4 * 4;                              \
                CVT_B_SC(s, k + 0, n, bPre[i].x); CVT_B_SC(s, k + 1, n, bPre[i].y); \
                CVT_B_SC(s, k + 2, n, bPre[i].z); CVT_B_SC(s, k + 3, n, bPre[i].w); \
            }                                                                   \
        }                                                                       \
    }

#define COMPUTE(s)                                                              \
    {                                                                           \
        uint32_t Ah[4][4], Al[4][4], Bh[4][2], Bl[4][2];                        \
        _Pragma("unroll")                                                       \
        for (int i = 0; i < 4; i++) {                                           \
            int row = wm * 64 + i * 16 + (lane & 15);                           \
            int col = (lane >> 4) << 3;                                         \
            ldsm_x4(Ah[i][0], Ah[i][1], Ah[i][2], Ah[i][3],                     \
                    smem_u32(&As[s][0][row][col]));                             \
            ldsm_x4(Al[i][0], Al[i][1], Al[i][2], Al[i][3],                     \
                    smem_u32(&As[s][1][row][col]));                             \
        }                                                                       \
        _Pragma("unroll")                                                       \
        for (int t2 = 0; t2 < 2; t2++) {                                        \
            int row = lane & 15;                                                \
            int col = wn * 32 + t2 * 16 + ((lane >> 4) << 3);                   \
            uint32_t r0, r1, r2, r3;                                            \
            ldsm_x4_t(r0, r1, r2, r3, smem_u32(&Bs[s][0][row][col]));           \
            Bh[t2*2][0] = r0; Bh[t2*2][1] = r1;                                 \
            Bh[t2*2+1][0] = r2; Bh[t2*2+1][1] = r3;                             \
            ldsm_x4_t(r0, r1, r2, r3, smem_u32(&Bs[s][1][row][col]));           \
            Bl[t2*2][0] = r0; Bl[t2*2][1] = r1;                                 \
            Bl[t2*2+1][0] = r2; Bl[t2*2+1][1] = r3;                             \
        }                                                                       \
        _Pragma("unroll")                                                       \
        for (int i = 0; i < 4; i++)                                             \
            _Pragma("unroll")                                                   \
            for (int j = 0; j < 4; j++) {                                       \
                mma_bf16(acc[i][j], Ah[i], Bh[j]);                              \
                mma_bf16(acc[i][j], Ah[i], Bl[j]);                              \
                mma_bf16(acc[i][j], Al[i], Bh[j]);                              \
            }                                                                   \
    }

    const int ktiles = (K + TBK - 1) / TBK;

    LOAD_REGS(0);
    STORE_SMEM(0);
    __syncthreads();

    for (int t = 0; t < ktiles; t++) {
        const int cur = t & 1;
        bool last = (t == ktiles - 1);
        if (!last) LOAD_REGS((t + 1) * TBK);
        COMPUTE(cur);
        if (!last) {
            STORE_SMEM(cur ^ 1);      // other stage: prior sync drained its readers
            __syncthreads();
        }
    }

    const int g  = lane >> 2;
    const int tg = lane & 3;
#pragma unroll
    for (int i = 0; i < 4; i++) {
        int r0w = m0 + wm * 64 + i * 16 + g;
        int r1w = r0w + 8;
#pragma unroll
        for (int j = 0; j < 4; j++) {
            int c0 = n0 + wn * 32 + j * 8 + tg * 2;
            if (c0 < N) {
                if (r0w < M) {
                    float2 v = make_float2(alpha * acc[i][j][0], alpha * acc[i][j][1]);
                    *(float2*)&C[(long long)r0w * ldc + c0] = v;
                }
                if (r1w < M) {
                    float2 v = make_float2(alpha * acc[i][j][2], alpha * acc[i][j][3]);
                    *(float2*)&C[(long long)r1w * ldc + c0] = v;
                }
            }
        }
    }

    // Fused stats epilogue: per-row max + per-z sum/sumsq of masked outputs.
    if (rm_st) {
        float ls = 0.f, ls2 = 0.f;
#pragma unroll
        for (int i = 0; i < 4; i++) {
            int r0w = m0 + wm * 64 + i * 16 + g;
            int r1w = r0w + 8;
            float m0v = -3.4e38f, m1v = -3.4e38f;
#pragma unroll
            for (int j = 0; j < 4; j++) {
                int c0 = n0 + wn * 32 + j * 8 + tg * 2;
                bool v0 = c0 < N, v1 = (c0 + 1) < N;
                if (r0w < M) {
                    if (v0) { float x = alpha * acc[i][j][0]; m0v = fmaxf(m0v, x); ls += x; ls2 += x * x; }
                    if (v1) { float x = alpha * acc[i][j][1]; m0v = fmaxf(m0v, x); ls += x; ls2 += x * x; }
                }
                if (r1w < M) {
                    if (v0) { float x = alpha * acc[i][j][2]; m1v = fmaxf(m1v, x); ls += x; ls2 += x * x; }
                    if (v1) { float x = alpha * acc[i][j][3]; m1v = fmaxf(m1v, x); ls += x; ls2 += x * x; }
                }
            }
            m0v = fmaxf(m0v, __shfl_xor_sync(~0u, m0v, 1));
            m0v = fmaxf(m0v, __shfl_xor_sync(~0u, m0v, 2));
            m1v = fmaxf(m1v, __shfl_xor_sync(~0u, m1v, 1));
            m1v = fmaxf(m1v, __shfl_xor_sync(~0u, m1v, 2));
            if (tg == 0) {
                if (r0w < M) atomicMaxF(&rm_st[(long long)z * 196 + r0w], m0v);
                if (r1w < M) atomicMaxF(&rm_st[(long long)z * 196 + r1w], m1v);
            }
        }
#pragma unroll
        for (int o = 16; o; o >>= 1) {
            ls  += __shfl_xor_sync(~0u, ls,  o);
            ls2 += __shfl_xor_sync(~0u, ls2, o);
        }
        if (lane == 0) {
            atomicAdd(&sum_st[z * 2 + 0], ls);
            atomicAdd(&sum_st[z * 2 + 1], ls2);
        }
    }
#undef LOAD_REGS
#undef STORE_SMEM
#undef COMPUTE
#undef CVT_B_SC
}

// ---------------------------------------------------------------------------
// Fused exp-softmax + P@V GEMM (one branch).  M=196, N=64, K=784 per z (128).
// gain computed inline from the fused-stats accumulators.
// ---------------------------------------------------------------------------
__global__ __launch_bounds__(256)
void attn_pv_kernel(const float* __restrict__ attn, const float* __restrict__ V,
                    float* __restrict__ ctx,
                    const float* __restrict__ rm, const float* __restrict__ sums)
{
    const int Mv = 196, Kv = 784;
    int z = blockIdx.z;               // 0..127 = b*4+h
    int bb = z >> 2, hh = z & 3;
    const float* A = attn + (long long)bb * 614656 + (long long)hh * 153664;
    const float* B = V    + (long long)bb * 200704 + hh * 64;
    float*       C = ctx  + (long long)bb * 50176  + hh * 64;
    float s  = sums[z * 2 + 0];
    float s2 = sums[z * 2 + 1];
    float mean = s / 153664.f;
    const float gv = rsqrtf(s2 / 153664.f - mean * mean + 1e-5f);
    const float* rmz = rm + (long long)z * 196;

    __shared__ __align__(16) __nv_bfloat16 As[2][2][128][A_STRIDE];    // 24 KB
    __shared__ __align__(16) __nv_bfloat16 Bs[2][2][TBK][PVB_STRIDE];  // 9 KB
    __shared__ float sden[128];

    const int tid  = threadIdx.x;
    const int lane = tid & 31;
    const int wid  = tid >> 5;
    const int wm   = wid >> 1;   // 0..3 : 32 rows each
    const int wn   = wid & 1;    // 0..1 : 32 cols each
    const int m0 = blockIdx.y * 128;

    if (tid < 128) sden[tid] = 0.f;

    float acc[2][4][4];
#pragma unroll
    for (int i = 0; i < 2; i++)
#pragma unroll
        for (int j = 0; j < 4; j++)
#pragma unroll
            for (int r = 0; r < 4; r++) acc[i][j][r] = 0.f;

    const int ar  = tid >> 2, ac4 = tid & 3;   // A: 64 rows/pass, 4 f4/row
    const int brr = tid >> 4, bc4 = tid & 15;  // B: 16 rows, 16 f4/row, 1 pass

    float4 aPre[2], bPre;
    int k0s = 0;

#define PV_LOAD(K0)                                                             \
    {                                                                           \
        int k0_ = (K0);                                                         \
        _Pragma("unroll")                                                       \
        for (int i = 0; i < 2; i++) {                                           \
            int gm = m0 + ar + i * 64, gk = k0_ + ac4 * 4;                      \
            aPre[i] = (gm < Mv && gk < Kv)                                      \
                ? *(const float4*)&A[(long long)gm * 784 + gk]                  \
                : make_float4(0.f, 0.f, 0.f, 0.f);                              \
        }                                                                       \
        {                                                                       \
            int gk = k0_ + brr;                                                 \
            bPre = (gk < Kv)                                                    \
                ? *(const float4*)&B[(long long)gk * 256 + bc4 * 4]             \
                : make_float4(0.f, 0.f, 0.f, 0.f);                              \
        }                                                                       \
        k0s = k0_;                                                              \
    }

#define PV_STORE(s)                                                             \
    {                                                                           \
        _Pragma("unroll")                                                       \
        for (int i = 0; i < 2; i++) {                                           \
            int m = ar + i * 64, gm = m0 + m;                                   \
            bool rok = (gm < Mv);                                               \
            float rmv = rok ? rmz[gm] : 0.f;                                    \
            float4 e4;                                                          \
            float vv[4] = { aPre[i].x, aPre[i].y, aPre[i].z, aPre[i].w };       \
            float ee[4];                                                        \
            _Pragma("unroll")                                                   \
            for (int cc = 0; cc < 4; cc++) {                                    \
                int gk = k0s + ac4 * 4 + cc;                                    \
                ee[cc] = (rok && gk < Kv) ? __expf(gv * (vv[cc] - rmv)) : 0.f;  \
            }                                                                   \
            e4 = make_float4(ee[0], ee[1], ee[2], ee[3]);                       \
            float part = ee[0] + ee[1] + ee[2] + ee[3];                         \
            cvt_store4(&As[s][0][m][ac4 * 4], &As[s][1][m][ac4 * 4], e4);       \
            if (part != 0.f) atomicAdd(&sden[m], part);                         \
        }                                                                       \
        {                                                                       \
            int k = brr, c = bc4 * 4;                                           \
            cvt_store4(&Bs[s][0][k][c], &Bs[s][1][k][c], bPre);                 \
        }                                                                       \
    }

    const int ktiles = (Kv + TBK - 1) / TBK;   // 49

    PV_LOAD(0);
    __syncthreads();           // sden init visible before first atomicAdd
    PV_STORE(0);
    __syncthreads();

    for (int t = 0; t < ktiles; t++) {
        const int cur = t & 1;
        bool last = (t == ktiles - 1);
        if (!last) PV_LOAD((t + 1) * TBK);
        {
            uint32_t Ah[2][4], Al[2][4], Bh[4][2], Bl[4][2];
#pragma unroll
            for (int i = 0; i < 2; i++) {
                int row = wm * 32 + i * 16 + (lane & 15);
                int col = (lane >> 4) << 3;
                ldsm_x4(Ah[i][0], Ah[i][1], Ah[i][2], Ah[i][3],
                        smem_u32(&As[cur][0][row][col]));
                ldsm_x4(Al[i][0], Al[i][1], Al[i][2], Al[i][3],
                        smem_u32(&As[cur][1][row][col]));
            }
            {
                int row = lane & 15;
                int col = wn * 32 + ((lane >> 4) << 3);
                uint32_t r0, r1, r2, r3;
                ldsm_x4_t(r0, r1, r2, r3, smem_u32(&Bs[cur][0][row][col]));
                Bh[0][0] = r0; Bh[0][1] = r1; Bh[1][0] = r2; Bh[1][1] = r3;
                ldsm_x4_t(r0, r1, r2, r3, smem_u32(&Bs[cur][0][row][col + 16]));
                Bh[2][0] = r0; Bh[2][1] = r1; Bh[3][0] = r2; Bh[3][1] = r3;
                ldsm_x4_t(r0, r1, r2, r3, smem_u32(&Bs[cur][1][row][col]));
                Bl[0][0] = r0; Bl[0][1] = r1; Bl[1][0] = r2; Bl[1][1] = r3;
                ldsm_x4_t(r0, r1, r2, r3, smem_u32(&Bs[cur][1][row][col + 16]));
                Bl[2][0] = r0; Bl[2][1] = r1; Bl[3][0] = r2; Bl[3][1] = r3;
            }
#pragma unroll
            for (int i = 0; i < 2; i++)
#pragma unroll
                for (int j = 0; j < 4; j++) {
                    mma_bf16(acc[i][j], Ah[i], Bh[j]);
                    mma_bf16(acc[i][j], Ah[i], Bl[j]);
                    mma_bf16(acc[i][j], Al[i], Bh[j]);
                }
        }
        if (!last) {
            PV_STORE(cur ^ 1);
            __syncthreads();
        }
    }

    const int g  = lane >> 2;
    const int tg = lane & 3;
#pragma unroll
    for (int i = 0; i < 2; i++) {
        int lr0 = wm * 32 + i * 16 + g;
        int lr1 = lr0 + 8;
        int r0w = m0 + lr0, r1w = m0 + lr1;
        float d0 = (r0w < Mv) ? 1.0f / sden[lr0] : 0.f;
        float d1 = (r1w < Mv) ? 1.0f / sden[lr1] : 0.f;
#pragma unroll
        for (int j = 0; j < 4; j++) {
            int c0 = wn * 32 + j * 8 + tg * 2;
            if (r0w < Mv) {
                float2 v = make_float2(acc[i][j][0] * d0, acc[i][j][1] * d0);
                *(float2*)&C[(long long)r0w * 256 + c0] = v;
            }
            if (r1w < Mv) {
                float2 v = make_float2(acc[i][j][2] * d1, acc[i][j][3] * d1);
                *(float2*)&C[(long long)r1w * 256 + c0] = v;
            }
        }
    }
#undef PV_LOAD
#undef PV_STORE
}

// ---------------------------------------------------------------------------
// Small helpers
// ---------------------------------------------------------------------------
__global__ void transpose_kernel(const float* __restrict__ src, float* __restrict__ dst,
                                 int M, int N)
{
    __shared__ float t[32][33];
    int x = blockIdx.x * 32 + threadIdx.x;
    int y0 = blockIdx.y * 32 + threadIdx.y;
#pragma unroll
    for (int i = 0; i < 32; i += 8) {
        int y = y0 + i;
        t[threadIdx.y + i][threadIdx.x] = (y < M && x < N) ? src[(long long)y * N + x] : 0.f;
    }
    __syncthreads();
    int xo = blockIdx.y * 32 + threadIdx.x;
    int yo0 = blockIdx.x * 32 + threadIdx.y;
#pragma unroll
    for (int i = 0; i < 32; i += 8) {
        int yo = yo0 + i;
        if (yo < N && xo < M) dst[(long long)yo * M + xo] = t[threadIdx.x][threadIdx.y + i];
    }
}

// Pack up to 4 separate buffers into one contiguous [grid.y][n] buffer.
__global__ void pack4_kernel(const float* __restrict__ p0, const float* __restrict__ p1,
                             const float* __restrict__ p2, const float* __restrict__ p3,
                             float* __restrict__ dst, long long n)
{
    long long i = (long long)blockIdx.x * 256 + threadIdx.x;
    int br = blockIdx.y;
    if (i < n) {
        const float* src = (br == 0) ? p0 : (br == 1) ? p1 : (br == 2) ? p2 : p3;
        dst[(long long)br * n + i] = src[i];
    }
}

// Reset fused-stats accumulators: rowmax (512*196) to -inf, sums (1024) to 0.
__global__ void stats_init_kernel(float* __restrict__ rm, float* __restrict__ sums)
{
    int i = blockIdx.x * 256 + threadIdx.x;
    if (i < 512 * 196) rm[i] = -3.4e38f;
    if (i < 1024) sums[i] = 0.f;
}

// KV_S[b, j*196+t, c] = T_hat[b, t, j*256 + c]
__global__ void kvs_kernel(const float* __restrict__ T, float* __restrict__ KVS)
{
    long long i = (long long)blockIdx.x * blockDim.x + threadIdx.x;
    if (i >= SZ_BNDC) return;
    int c = (int)(i & 255);
    long long t2 = i >> 8;
    int n = (int)(t2 % 784);
    int b = (int)(t2 / 784);
    int j = n / 196, t = n % 196;
    KVS[i] = T[((long long)b * 196 + t) * 1024 + (long long)j * 256 + c];
}

// Plain row softmax (SATAT scores, 196 cols)
__global__ void softmax_kernel(float* __restrict__ X, int cols)
{
    int row = blockIdx.x;
    float* x = X + (long long)row * cols;
    int tid = threadIdx.x;
    __shared__ float red[256];

    float m = -1e30f;
    for (int c = tid; c < cols; c += 256) m = fmaxf(m, x[c]);
    red[tid] = m; __syncthreads();
    for (int s = 128; s > 0; s >>= 1) {
        if (tid < s) red[tid] = fmaxf(red[tid], red[tid + s]);
        __syncthreads();
    }
    m = red[0]; __syncthreads();

    float sum = 0.f;
    for (int c = tid; c < cols; c += 256) {
        float e = __expf(x[c] - m);
        x[c] = e; sum += e;
    }
    red[tid] = sum; __syncthreads();
    for (int s = 128; s > 0; s >>= 1) {
        if (tid < s) red[tid] += red[tid + s];
        __syncthreads();
    }
    float inv = 1.0f / red[0];
    for (int c = tid; c < cols; c += 256) x[c] *= inv;
}

// ---------------------------------------------------------------------------
// Host-side driver
// ---------------------------------------------------------------------------
static inline void gemm(int tb,
                        const float* A, const float* B, float* C,
                        int M, int N, int K, int lda, int ldb, int ldc,
                        long long sAb, long long sAh,
                        long long sBb, long long sBh,
                        long long sCb, long long sCh,
                        int batch, int nh, float alpha,
                        float* rm_st = nullptr, float* sum_st = nullptr)
{
    dim3 g((N + TBN - 1) / TBN, (M + TBM - 1) / TBM, batch), b(256);
    if (tb)
        gemm_mma<true><<<g, b>>>(A, B, C, M, N, K, lda, ldb, ldc,
                                 sAb, sAh, sBb, sBh, sCb, sCh, nh, alpha,
                                 rm_st, sum_st);
    else
        gemm_mma<false><<<g, b>>>(A, B, C, M, N, K, lda, ldb, ldc,
                                  sAb, sAh, sBb, sBh, sCb, sCh, nh, alpha,
                                  rm_st, sum_st);
}

extern "C" void kernel_launch(void* const* d_in, const int* in_sizes, int n_in,
                              void* d_out, int out_size)
{
    const float* emb[4] = { (const float*)d_in[0], (const float*)d_in[1],
                            (const float*)d_in[2], (const float*)d_in[3] };
    const float* emb_C = (const float*)d_in[4];
    const float* Wq_c  = (const float*)d_in[5];
    const float* Wk_c  = (const float*)d_in[6];
    const float* Wv_c  = (const float*)d_in[7];
    const float* Wo_c  = (const float*)d_in[8];
    const float* Wq[4] = { (const float*)d_in[9],  (const float*)d_in[10],
                           (const float*)d_in[11], (const float*)d_in[12] };
    const float* Wk    = (const float*)d_in[13];
    const float* Wv    = (const float*)d_in[14];
    const float* Wo[4] = { (const float*)d_in[15], (const float*)d_in[16],
                           (const float*)d_in[17], (const float*)d_in[18] };
    float* out = (float*)d_out;

    float *q3, *k3, *v3, *sc, *oat, *that, *kvs, *Kb, *Vb, *attn, *ctxp;
    float *rowmax, *WkT, *WvT, *WqT;
    cudaGetSymbolAddress((void**)&q3,    g_q3);
    cudaGetSymbolAddress((void**)&k3,    g_k3);
    cudaGetSymbolAddress((void**)&v3,    g_v3);
    cudaGetSymbolAddress((void**)&sc,    g_sc);
    cudaGetSymbolAddress((void**)&oat,   g_oat);
    cudaGetSymbolAddress((void**)&that,  g_that);
    cudaGetSymbolAddress((void**)&kvs,   g_kvs);
    cudaGetSymbolAddress((void**)&Kb,    g_Kb);
    cudaGetSymbolAddress((void**)&Vb,    g_Vb);
    cudaGetSymbolAddress((void**)&attn,  g_attn);
    cudaGetSymbolAddress((void**)&ctxp,  g_ctx);
    cudaGetSymbolAddress((void**)&rowmax,g_rowmax);
    cudaGetSymbolAddress((void**)&WkT,   g_WkT);
    cudaGetSymbolAddress((void**)&WvT,   g_WvT);
    cudaGetSymbolAddress((void**)&WqT,   g_WqT);

    // ---------------- Weight pre-transposes + stats init ----------------
    {
        dim3 b(32, 8);
        dim3 g784((784 + 31) / 32, (784 + 31) / 32);
        transpose_kernel<<<g784, b>>>(Wk, WkT, 784, 784);
        transpose_kernel<<<g784, b>>>(Wv, WvT, 784, 784);
        dim3 g196((196 + 31) / 32, (196 + 31) / 32);
        for (int i = 0; i < 4; i++)
            transpose_kernel<<<g196, b>>>(Wq[i], WqT + (long long)i * 38416, 196, 196);
        stats_init_kernel<<<(512 * 196 + 255) / 256, 256>>>(rowmax, ctxp);
    }

    // ---------------- Stage A: SATAT over emb_C ----------------
    float* Wqkv = q3;                       // packed Wq_c|Wk_c|Wv_c
    float* qv   = attn;                     // q slab
    float* kvh  = attn + SZ_BNDC;           // k slab
    float* vv   = attn + 2 * SZ_BNDC;       // v slab
    pack4_kernel<<<dim3(4096, 3), 256>>>(Wq_c, Wk_c, Wv_c, Wv_c, Wqkv, 1048576LL);
    gemm(0, emb_C, Wqkv, qv, 6272, 1024, 1024, 1024, 1024, 1024,
         0, 0, 1048576, 0, SZ_BNDC, 0, 3, 1, 1.0f);

    gemm(1, qv, kvh, sc, 196, 196, 256, 1024, 1024, 196,
         200704, 256, 200704, 256, 153664, 38416, 128, 4, 0.0625f);
    softmax_kernel<<<25088, 256>>>(sc, 196);
    gemm(0, sc, vv, oat, 196, 256, 196, 196, 1024, 1024,
         153664, 38416, 200704, 256, 200704, 256, 128, 4, 1.0f);
    gemm(0, oat, Wo_c, that, 6272, 1024, 1024, 1024, 1024, 1024,
         0, 0, 0, 0, 0, 0, 1, 1, 1.0f);

    // ---------------- Stage B: KV token mix (fused K+V) ----------------
    kvs_kernel<<<(unsigned)((SZ_BNDC + 255) / 256), 256>>>(that, kvs);
    gemm(0, WkT, kvs, Kb, 784, 256, 784, 784, 256, 256,
         (long long)(WvT - WkT), 0, 0, 200704,
         (long long)(Vb - Kb), 200704, 64, 32, 1.0f);

    // ---------------- Stage C: 4 branches ----------------
    float* embP = q3;
    float* Qb4  = k3;
    float* WoP  = v3;
    float* ctx4 = oat;
    float* sums = ctxp;           // 1024 floats (512 z * 2)
    pack4_kernel<<<dim3((unsigned)((SZ_Q + 255) / 256), 4), 256>>>(
        emb[0], emb[1], emb[2], emb[3], embP, SZ_Q);
    pack4_kernel<<<dim3(256, 4), 256>>>(
        Wo[0], Wo[1], Wo[2], Wo[3], WoP, 65536);

    // Batched Q-mix: z = br*32 + b  (512 blocks, one launch)
    gemm(0, WqT, embP, Qb4, 196, 256, 196, 196, 256, 256,
         38416, 0, SZ_Q, 50176, SZ_Q, 50176, 128, 32, 1.0f);

    // QK (with fused stats epilogue) + fused softmax-PV per branch
    for (int br = 0; br < 4; br++) {
        const float* Qb = Qb4 + (long long)br * SZ_Q;
        float* rm_br  = rowmax + (long long)br * 128 * 196;
        float* sum_br = sums + (long long)br * 256;
        gemm(1, Qb, Kb, attn, 196, 784, 64, 256, 256, 784,
             50176, 64, 200704, 64, 614656, 153664, 128, 4, 1.0f,
             rm_br, sum_br);
        dim3 g(1, 2, 128), b(256);
        attn_pv_kernel<<<g, b>>>(attn, Vb, ctx4 + (long long)br * SZ_Q,
                                 rm_br, sum_br);
    }

    // Batched Wo: z = br  (392 blocks, one launch)
    gemm(0, ctx4, WoP, out, 6272, 256, 256, 256, 256, 256,
         SZ_Q, 0, 65536, 0, SZ_Q, 0, 4, 1, 1.0f);
}

// round 15
// speedup vs baseline: 1.0191x; 1.0191x over previous
#include <cuda_runtime.h>
#include <cuda_bf16.h>
#include <cstdint>

// ---------------------------------------------------------------------------
// Problem constants: B=32, N=196, DQ=256, DC=1024, H=4, DH=64, DHC=256, 4N=784
// ---------------------------------------------------------------------------

#define SZ_BNDC   6422528LL   // 32*196*1024  (also 32*784*256)
#define SZ_SC     4917248LL   // 32*4*196*196
#define SZ_Q      1605632LL   // 32*196*256
#define SZ_ATTN  19668992LL   // 32*4*196*784 (one branch)

__device__ float g_q3[SZ_BNDC];
__device__ float g_k3[SZ_BNDC];
__device__ float g_v3[SZ_BNDC];
__device__ float g_sc[SZ_SC];
__device__ float g_oat[SZ_BNDC];
__device__ float g_that[SZ_BNDC];
__device__ float g_kvs[SZ_BNDC];
__device__ float g_Kb[SZ_BNDC];
__device__ float g_Vb[SZ_BNDC];
__device__ float g_Qb[SZ_Q];
__device__ float g_attn[SZ_ATTN];
__device__ float g_ctx[SZ_Q];        // stats sum/sumsq accumulators (1024 used)
__device__ float g_gain[128];
__device__ float g_rowmax[512 * 196];
__device__ float g_WkT[614656];       // 784*784
__device__ float g_WvT[614656];
__device__ float g_WqT[4 * 38416];    // 4 * 196*196

// ---------------------------------------------------------------------------
// PTX helpers
// ---------------------------------------------------------------------------
__device__ __forceinline__ uint32_t smem_u32(const void* p) {
    return (uint32_t)__cvta_generic_to_shared(p);
}

__device__ __forceinline__ void ldsm_x4(uint32_t& r0, uint32_t& r1,
                                        uint32_t& r2, uint32_t& r3, uint32_t addr) {
    asm volatile("ldmatrix.sync.aligned.m8n8.x4.shared.b16 {%0,%1,%2,%3},[%4];"
                 : "=r"(r0), "=r"(r1), "=r"(r2), "=r"(r3) : "r"(addr));
}

__device__ __forceinline__ void ldsm_x4_t(uint32_t& r0, uint32_t& r1,
                                          uint32_t& r2, uint32_t& r3, uint32_t addr) {
    asm volatile("ldmatrix.sync.aligned.m8n8.x4.trans.shared.b16 {%0,%1,%2,%3},[%4];"
                 : "=r"(r0), "=r"(r1), "=r"(r2), "=r"(r3) : "r"(addr));
}

__device__ __forceinline__ void mma_bf16(float* c, const uint32_t* a, const uint32_t* b) {
    asm volatile("mma.sync.aligned.m16n8k16.row.col.f32.bf16.bf16.f32 "
                 "{%0,%1,%2,%3},{%4,%5,%6,%7},{%8,%9},{%0,%1,%2,%3};"
                 : "+f"(c[0]), "+f"(c[1]), "+f"(c[2]), "+f"(c[3])
                 : "r"(a[0]), "r"(a[1]), "r"(a[2]), "r"(a[3]),
                   "r"(b[0]), "r"(b[1]));
}

__device__ __forceinline__ void atomicMaxF(float* a, float v) {
    int old = __float_as_int(*a);
    while (__int_as_float(old) < v) {
        int assumed = old;
        old = atomicCAS((int*)a, assumed, __float_as_int(v));
        if (old == assumed) break;
    }
}

// Split-convert 4 consecutive fp32 into hi/lo bf16 planes with ONE 8-byte
// store per plane (addresses are 8B-aligned: row strides 24/136/72 bf16).
__device__ __forceinline__ void cvt_store4(__nv_bfloat16* hi, __nv_bfloat16* lo,
                                           float4 v) {
    __nv_bfloat16 h0 = __float2bfloat16(v.x), h1 = __float2bfloat16(v.y);
    __nv_bfloat16 h2 = __float2bfloat16(v.z), h3 = __float2bfloat16(v.w);
    __nv_bfloat162 hA = __halves2bfloat162(h0, h1);
    __nv_bfloat162 hB = __halves2bfloat162(h2, h3);
    uint2 hp; hp.x = *(uint32_t*)&hA; hp.y = *(uint32_t*)&hB;
    *(uint2*)hi = hp;
    __nv_bfloat162 lA = __halves2bfloat162(
        __float2bfloat16(v.x - __bfloat162float(h0)),
        __float2bfloat16(v.y - __bfloat162float(h1)));
    __nv_bfloat162 lB = __halves2bfloat162(
        __float2bfloat16(v.z - __bfloat162float(h2)),
        __float2bfloat16(v.w - __bfloat162float(h3)));
    uint2 lp; lp.x = *(uint32_t*)&lA; lp.y = *(uint32_t*)&lB;
    *(uint2*)lo = lp;
}

// ---------------------------------------------------------------------------
// Tile geometry: 128x128 block tile, TBK=16, double-buffered STATIC smem.
// ---------------------------------------------------------------------------
#define TBM 128
#define TBN 128
#define TBK 16
#define A_STRIDE 24                 // TBK + 8 pad
#define B_STRIDE 136                // TBN + 8 pad
#define PVB_STRIDE 72               // 64 + 8 pad

// ---------------------------------------------------------------------------
// Tensor-core batched GEMM, split-bf16 (3 MMA) fp32 emulation.
// STATS is a COMPILE-TIME flag: only the QK instantiation carries the fused
// stats epilogue; all other launches are register-identical to the round-12
// kernel.  __launch_bounds__(256,2) pins 2 blocks/SM for both variants.
// ---------------------------------------------------------------------------
template<bool TB, bool STATS>
__global__ __launch_bounds__(256, 2)
void gemm_mma(const float* __restrict__ A, const float* __restrict__ B,
              float* __restrict__ C,
              int M, int N, int K, int lda, int ldb, int ldc,
              long long sAb, long long sAh, long long sBb, long long sBh,
              long long sCb, long long sCh, int nh, float alpha,
              float* rm_st, float* sum_st)
{
    int z  = blockIdx.z;
    int bb = z / nh, hh = z % nh;
    A += bb * sAb + hh * sAh;
    B += bb * sBb + hh * sBh;
    C += bb * sCb + hh * sCh;

    __shared__ __align__(16) __nv_bfloat16 As[2][2][TBM][A_STRIDE];  // 24.0 KB
    __shared__ __align__(16) __nv_bfloat16 Bs[2][2][TBK][B_STRIDE];  // 17.0 KB

    const int tid  = threadIdx.x;
    const int lane = tid & 31;
    const int wid  = tid >> 5;
    const int wm   = wid >> 2;
    const int wn   = wid & 3;
    const int m0 = blockIdx.y * TBM, n0 = blockIdx.x * TBN;

    float acc[4][4][4];
#pragma unroll
    for (int i = 0; i < 4; i++)
#pragma unroll
        for (int j = 0; j < 4; j++)
#pragma unroll
            for (int r = 0; r < 4; r++) acc[i][j][r] = 0.f;

    const int ar  = tid >> 2, ac4 = tid & 3;    // A: 64 rows/pass, 4 f4/row
    const int bkr = tid >> 5, bc4 = tid & 31;   // B NN: 8 k-rows/pass, 32 f4/row
    const int bnr = tid >> 2, bk4 = tid & 3;    // B NT: 64 n-rows/pass, 4 f4/row

    float4 aPre[2], bPre[2];

#define LOAD_REGS(K0)                                                           \
    {                                                                           \
        int k0_ = (K0);                                                         \
        _Pragma("unroll")                                                       \
        for (int i = 0; i < 2; i++) {                                           \
            int gm = m0 + ar + i * 64, gk = k0_ + ac4 * 4;                      \
            aPre[i] = (gm < M && gk < K)                                        \
                ? *(const float4*)&A[(long long)gm * lda + gk]                  \
                : make_float4(0.f, 0.f, 0.f, 0.f);                              \
        }                                                                       \
        if (!TB) {                                                              \
            _Pragma("unroll")                                                   \
            for (int i = 0; i < 2; i++) {                                       \
                int gk = k0_ + bkr + i * 8, gn = n0 + bc4 * 4;                  \
                bPre[i] = (gk < K && gn < N)                                    \
                    ? *(const float4*)&B[(long long)gk * ldb + gn]              \
                    : make_float4(0.f, 0.f, 0.f, 0.f);                          \
            }                                                                   \
        } else {                                                                \
            _Pragma("unroll")                                                   \
            for (int i = 0; i < 2; i++) {                                       \
                int gn = n0 + bnr + i * 64, gk = k0_ + bk4 * 4;                 \
                bPre[i] = (gn < N && gk < K)                                    \
                    ? *(const float4*)&B[(long long)gn * ldb + gk]              \
                    : make_float4(0.f, 0.f, 0.f, 0.f);                          \
            }                                                                   \
        }                                                                       \
    }

#define CVT_B_SC(s, dr, dc, f)                                                  \
    {                                                                           \
        __nv_bfloat16 hi_ = __float2bfloat16(f);                                \
        Bs[s][0][dr][dc] = hi_;                                                 \
        Bs[s][1][dr][dc] = __float2bfloat16((f) - __bfloat162float(hi_));       \
    }

#define STORE_SMEM(s)                                                           \
    {                                                                           \
        _Pragma("unroll")                                                       \
        for (int i = 0; i < 2; i++) {                                           \
            int m = ar + i * 64, c = ac4 * 4;                                   \
            cvt_store4(&As[s][0][m][c], &As[s][1][m][c], aPre[i]);              \
        }                                                                       \
        if (!TB) {                                                              \
            _Pragma("unroll")                                                   \
            for (int i = 0; i < 2; i++) {                                       \
                int k = bkr + i * 8, c = bc4 * 4;                               \
                cvt_store4(&Bs[s][0][k][c], &Bs[s][1][k][c], bPre[i]);          \
            }                                                                   \
        } else {                                                                \
            _Pragma("unroll")                                                   \
            for (int i = 0; i < 2; i++) {                                       \
                int n = bnr + i * 64, k = bk4 * 4;                              \
                CVT_B_SC(s, k + 0, n, bPre[i].x); CVT_B_SC(s, k + 1, n, bPre[i].y); \
                CVT_B_SC(s, k + 2, n, bPre[i].z); CVT_B_SC(s, k + 3, n, bPre[i].w); \
            }                                                                   \
        }                                                                       \
    }

#define COMPUTE(s)                                                              \
    {                                                                           \
        uint32_t Ah[4][4], Al[4][4], Bh[4][2], Bl[4][2];                        \
        _Pragma("unroll")                                                       \
        for (int i = 0; i < 4; i++) {                                           \
            int row = wm * 64 + i * 16 + (lane & 15);                           \
            int col = (lane >> 4) << 3;                                         \
            ldsm_x4(Ah[i][0], Ah[i][1], Ah[i][2], Ah[i][3],                     \
                    smem_u32(&As[s][0][row][col]));                             \
            ldsm_x4(Al[i][0], Al[i][1], Al[i][2], Al[i][3],                     \
                    smem_u32(&As[s][1][row][col]));                             \
        }                                                                       \
        _Pragma("unroll")                                                       \
        for (int t2 = 0; t2 < 2; t2++) {                                        \
            int row = lane & 15;                                                \
            int col = wn * 32 + t2 * 16 + ((lane >> 4) << 3);                   \
            uint32_t r0, r1, r2, r3;                                            \
            ldsm_x4_t(r0, r1, r2, r3, smem_u32(&Bs[s][0][row][col]));           \
            Bh[t2*2][0] = r0; Bh[t2*2][1] = r1;                                 \
            Bh[t2*2+1][0] = r2; Bh[t2*2+1][1] = r3;                             \
            ldsm_x4_t(r0, r1, r2, r3, smem_u32(&Bs[s][1][row][col]));           \
            Bl[t2*2][0] = r0; Bl[t2*2][1] = r1;                                 \
            Bl[t2*2+1][0] = r2; Bl[t2*2+1][1] = r3;                             \
        }                                                                       \
        _Pragma("unroll")                                                       \
        for (int i = 0; i < 4; i++)                                             \
            _Pragma("unroll")                                                   \
            for (int j = 0; j < 4; j++) {                                       \
                mma_bf16(acc[i][j], Ah[i], Bh[j]);                              \
                mma_bf16(acc[i][j], Ah[i], Bl[j]);                              \
                mma_bf16(acc[i][j], Al[i], Bh[j]);                              \
            }                                                                   \
    }

    const int ktiles = (K + TBK - 1) / TBK;

    LOAD_REGS(0);
    STORE_SMEM(0);
    __syncthreads();

    for (int t = 0; t < ktiles; t++) {
        const int cur = t & 1;
        bool last = (t == ktiles - 1);
        if (!last) LOAD_REGS((t + 1) * TBK);
        COMPUTE(cur);
        if (!last) {
            STORE_SMEM(cur ^ 1);      // other stage: prior sync drained its readers
            __syncthreads();
        }
    }

    const int g  = lane >> 2;
    const int tg = lane & 3;
#pragma unroll
    for (int i = 0; i < 4; i++) {
        int r0w = m0 + wm * 64 + i * 16 + g;
        int r1w = r0w + 8;
#pragma unroll
        for (int j = 0; j < 4; j++) {
            int c0 = n0 + wn * 32 + j * 8 + tg * 2;
            if (c0 < N) {
                if (r0w < M) {
                    float2 v = make_float2(alpha * acc[i][j][0], alpha * acc[i][j][1]);
                    *(float2*)&C[(long long)r0w * ldc + c0] = v;
                }
                if (r1w < M) {
                    float2 v = make_float2(alpha * acc[i][j][2], alpha * acc[i][j][3]);
                    *(float2*)&C[(long long)r1w * ldc + c0] = v;
                }
            }
        }
    }

    if (STATS) {
        // Fused stats epilogue (QK only): per-row max + per-z sum/sumsq.
        float ls = 0.f, ls2 = 0.f;
#pragma unroll
        for (int i = 0; i < 4; i++) {
            int r0w = m0 + wm * 64 + i * 16 + g;
            int r1w = r0w + 8;
            float m0v = -3.4e38f, m1v = -3.4e38f;
#pragma unroll
            for (int j = 0; j < 4; j++) {
                int c0 = n0 + wn * 32 + j * 8 + tg * 2;
                bool v0 = c0 < N, v1 = (c0 + 1) < N;
                if (r0w < M) {
                    if (v0) { float x = alpha * acc[i][j][0]; m0v = fmaxf(m0v, x); ls += x; ls2 += x * x; }
                    if (v1) { float x = alpha * acc[i][j][1]; m0v = fmaxf(m0v, x); ls += x; ls2 += x * x; }
                }
                if (r1w < M) {
                    if (v0) { float x = alpha * acc[i][j][2]; m1v = fmaxf(m1v, x); ls += x; ls2 += x * x; }
                    if (v1) { float x = alpha * acc[i][j][3]; m1v = fmaxf(m1v, x); ls += x; ls2 += x * x; }
                }
            }
            m0v = fmaxf(m0v, __shfl_xor_sync(~0u, m0v, 1));
            m0v = fmaxf(m0v, __shfl_xor_sync(~0u, m0v, 2));
            m1v = fmaxf(m1v, __shfl_xor_sync(~0u, m1v, 1));
            m1v = fmaxf(m1v, __shfl_xor_sync(~0u, m1v, 2));
            if (tg == 0) {
                if (r0w < M) atomicMaxF(&rm_st[(long long)z * 196 + r0w], m0v);
                if (r1w < M) atomicMaxF(&rm_st[(long long)z * 196 + r1w], m1v);
            }
        }
#pragma unroll
        for (int o = 16; o; o >>= 1) {
            ls  += __shfl_xor_sync(~0u, ls,  o);
            ls2 += __shfl_xor_sync(~0u, ls2, o);
        }
        if (lane == 0) {
            atomicAdd(&sum_st[z * 2 + 0], ls);
            atomicAdd(&sum_st[z * 2 + 1], ls2);
        }
    }
#undef LOAD_REGS
#undef STORE_SMEM
#undef COMPUTE
#undef CVT_B_SC
}

// ---------------------------------------------------------------------------
// Fused exp-softmax + P@V GEMM (one branch).  M=196, N=64, K=784 per z (128).
// gain computed inline from the fused-stats accumulators.
// ---------------------------------------------------------------------------
__global__ __launch_bounds__(256)
void attn_pv_kernel(const float* __restrict__ attn, const float* __restrict__ V,
                    float* __restrict__ ctx,
                    const float* __restrict__ rm, const float* __restrict__ sums)
{
    const int Mv = 196, Kv = 784;
    int z = blockIdx.z;               // 0..127 = b*4+h
    int bb = z >> 2, hh = z & 3;
    const float* A = attn + (long long)bb * 614656 + (long long)hh * 153664;
    const float* B = V    + (long long)bb * 200704 + hh * 64;
    float*       C = ctx  + (long long)bb * 50176  + hh * 64;
    float s  = sums[z * 2 + 0];
    float s2 = sums[z * 2 + 1];
    float mean = s / 153664.f;
    const float gv = rsqrtf(s2 / 153664.f - mean * mean + 1e-5f);
    const float* rmz = rm + (long long)z * 196;

    __shared__ __align__(16) __nv_bfloat16 As[2][2][128][A_STRIDE];    // 24 KB
    __shared__ __align__(16) __nv_bfloat16 Bs[2][2][TBK][PVB_STRIDE];  // 9 KB
    __shared__ float sden[128];

    const int tid  = threadIdx.x;
    const int lane = tid & 31;
    const int wid  = tid >> 5;
    const int wm   = wid >> 1;   // 0..3 : 32 rows each
    const int wn   = wid & 1;    // 0..1 : 32 cols each
    const int m0 = blockIdx.y * 128;

    if (tid < 128) sden[tid] = 0.f;

    float acc[2][4][4];
#pragma unroll
    for (int i = 0; i < 2; i++)
#pragma unroll
        for (int j = 0; j < 4; j++)
#pragma unroll
            for (int r = 0; r < 4; r++) acc[i][j][r] = 0.f;

    const int ar  = tid >> 2, ac4 = tid & 3;   // A: 64 rows/pass, 4 f4/row
    const int brr = tid >> 4, bc4 = tid & 15;  // B: 16 rows, 16 f4/row, 1 pass

    float4 aPre[2], bPre;
    int k0s = 0;

#define PV_LOAD(K0)                                                             \
    {                                                                           \
        int k0_ = (K0);                                                         \
        _Pragma("unroll")                                                       \
        for (int i = 0; i < 2; i++) {                                           \
            int gm = m0 + ar + i * 64, gk = k0_ + ac4 * 4;                      \
            aPre[i] = (gm < Mv && gk < Kv)                                      \
                ? *(const float4*)&A[(long long)gm * 784 + gk]                  \
                : make_float4(0.f, 0.f, 0.f, 0.f);                              \
        }                                                                       \
        {                                                                       \
            int gk = k0_ + brr;                                                 \
            bPre = (gk < Kv)                                                    \
                ? *(const float4*)&B[(long long)gk * 256 + bc4 * 4]             \
                : make_float4(0.f, 0.f, 0.f, 0.f);                              \
        }                                                                       \
        k0s = k0_;                                                              \
    }

#define PV_STORE(s)                                                             \
    {                                                                           \
        _Pragma("unroll")                                                       \
        for (int i = 0; i < 2; i++) {                                           \
            int m = ar + i * 64, gm = m0 + m;                                   \
            bool rok = (gm < Mv);                                               \
            float rmv = rok ? rmz[gm] : 0.f;                                    \
            float4 e4;                                                          \
            float vv[4] = { aPre[i].x, aPre[i].y, aPre[i].z, aPre[i].w };       \
            float ee[4];                                                        \
            _Pragma("unroll")                                                   \
            for (int cc = 0; cc < 4; cc++) {                                    \
                int gk = k0s + ac4 * 4 + cc;                                    \
                ee[cc] = (rok && gk < Kv) ? __expf(gv * (vv[cc] - rmv)) : 0.f;  \
            }                                                                   \
            e4 = make_float4(ee[0], ee[1], ee[2], ee[3]);                       \
            float part = ee[0] + ee[1] + ee[2] + ee[3];                         \
            cvt_store4(&As[s][0][m][ac4 * 4], &As[s][1][m][ac4 * 4], e4);       \
            if (part != 0.f) atomicAdd(&sden[m], part);                         \
        }                                                                       \
        {                                                                       \
            int k = brr, c = bc4 * 4;                                           \
            cvt_store4(&Bs[s][0][k][c], &Bs[s][1][k][c], bPre);                 \
        }                                                                       \
    }

    const int ktiles = (Kv + TBK - 1) / TBK;   // 49

    PV_LOAD(0);
    __syncthreads();           // sden init visible before first atomicAdd
    PV_STORE(0);
    __syncthreads();

    for (int t = 0; t < ktiles; t++) {
        const int cur = t & 1;
        bool last = (t == ktiles - 1);
        if (!last) PV_LOAD((t + 1) * TBK);
        {
            uint32_t Ah[2][4], Al[2][4], Bh[4][2], Bl[4][2];
#pragma unroll
            for (int i = 0; i < 2; i++) {
                int row = wm * 32 + i * 16 + (lane & 15);
                int col = (lane >> 4) << 3;
                ldsm_x4(Ah[i][0], Ah[i][1], Ah[i][2], Ah[i][3],
                        smem_u32(&As[cur][0][row][col]));
                ldsm_x4(Al[i][0], Al[i][1], Al[i][2], Al[i][3],
                        smem_u32(&As[cur][1][row][col]));
            }
            {
                int row = lane & 15;
                int col = wn * 32 + ((lane >> 4) << 3);
                uint32_t r0, r1, r2, r3;
                ldsm_x4_t(r0, r1, r2, r3, smem_u32(&Bs[cur][0][row][col]));
                Bh[0][0] = r0; Bh[0][1] = r1; Bh[1][0] = r2; Bh[1][1] = r3;
                ldsm_x4_t(r0, r1, r2, r3, smem_u32(&Bs[cur][0][row][col + 16]));
                Bh[2][0] = r0; Bh[2][1] = r1; Bh[3][0] = r2; Bh[3][1] = r3;
                ldsm_x4_t(r0, r1, r2, r3, smem_u32(&Bs[cur][1][row][col]));
                Bl[0][0] = r0; Bl[0][1] = r1; Bl[1][0] = r2; Bl[1][1] = r3;
                ldsm_x4_t(r0, r1, r2, r3, smem_u32(&Bs[cur][1][row][col + 16]));
                Bl[2][0] = r0; Bl[2][1] = r1; Bl[3][0] = r2; Bl[3][1] = r3;
            }
#pragma unroll
            for (int i = 0; i < 2; i++)
#pragma unroll
                for (int j = 0; j < 4; j++) {
                    mma_bf16(acc[i][j], Ah[i], Bh[j]);
                    mma_bf16(acc[i][j], Ah[i], Bl[j]);
                    mma_bf16(acc[i][j], Al[i], Bh[j]);
                }
        }
        if (!last) {
            PV_STORE(cur ^ 1);
            __syncthreads();
        }
    }

    const int g  = lane >> 2;
    const int tg = lane & 3;
#pragma unroll
    for (int i = 0; i < 2; i++) {
        int lr0 = wm * 32 + i * 16 + g;
        int lr1 = lr0 + 8;
        int r0w = m0 + lr0, r1w = m0 + lr1;
        float d0 = (r0w < Mv) ? 1.0f / sden[lr0] : 0.f;
        float d1 = (r1w < Mv) ? 1.0f / sden[lr1] : 0.f;
#pragma unroll
        for (int j = 0; j < 4; j++) {
            int c0 = wn * 32 + j * 8 + tg * 2;
            if (r0w < Mv) {
                float2 v = make_float2(acc[i][j][0] * d0, acc[i][j][1] * d0);
                *(float2*)&C[(long long)r0w * 256 + c0] = v;
            }
            if (r1w < Mv) {
                float2 v = make_float2(acc[i][j][2] * d1, acc[i][j][3] * d1);
                *(float2*)&C[(long long)r1w * 256 + c0] = v;
            }
        }
    }
#undef PV_LOAD
#undef PV_STORE
}

// ---------------------------------------------------------------------------
// Small helpers
// ---------------------------------------------------------------------------
__global__ void transpose_kernel(const float* __restrict__ src, float* __restrict__ dst,
                                 int M, int N)
{
    __shared__ float t[32][33];
    int x = blockIdx.x * 32 + threadIdx.x;
    int y0 = blockIdx.y * 32 + threadIdx.y;
#pragma unroll
    for (int i = 0; i < 32; i += 8) {
        int y = y0 + i;
        t[threadIdx.y + i][threadIdx.x] = (y < M && x < N) ? src[(long long)y * N + x] : 0.f;
    }
    __syncthreads();
    int xo = blockIdx.y * 32 + threadIdx.x;
    int yo0 = blockIdx.x * 32 + threadIdx.y;
#pragma unroll
    for (int i = 0; i < 32; i += 8) {
        int yo = yo0 + i;
        if (yo < N && xo < M) dst[(long long)yo * M + xo] = t[threadIdx.x][threadIdx.y + i];
    }
}

// Pack up to 4 separate buffers into one contiguous [grid.y][n] buffer.
__global__ void pack4_kernel(const float* __restrict__ p0, const float* __restrict__ p1,
                             const float* __restrict__ p2, const float* __restrict__ p3,
                             float* __restrict__ dst, long long n)
{
    long long i = (long long)blockIdx.x * 256 + threadIdx.x;
    int br = blockIdx.y;
    if (i < n) {
        const float* src = (br == 0) ? p0 : (br == 1) ? p1 : (br == 2) ? p2 : p3;
        dst[(long long)br * n + i] = src[i];
    }
}

// Reset fused-stats accumulators: rowmax (512*196) to -inf, sums (1024) to 0.
__global__ void stats_init_kernel(float* __restrict__ rm, float* __restrict__ sums)
{
    int i = blockIdx.x * 256 + threadIdx.x;
    if (i < 512 * 196) rm[i] = -3.4e38f;
    if (i < 1024) sums[i] = 0.f;
}

// KV_S[b, j*196+t, c] = T_hat[b, t, j*256 + c]
__global__ void kvs_kernel(const float* __restrict__ T, float* __restrict__ KVS)
{
    long long i = (long long)blockIdx.x * blockDim.x + threadIdx.x;
    if (i >= SZ_BNDC) return;
    int c = (int)(i & 255);
    long long t2 = i >> 8;
    int n = (int)(t2 % 784);
    int b = (int)(t2 / 784);
    int j = n / 196, t = n % 196;
    KVS[i] = T[((long long)b * 196 + t) * 1024 + (long long)j * 256 + c];
}

// Plain row softmax (SATAT scores, 196 cols)
__global__ void softmax_kernel(float* __restrict__ X, int cols)
{
    int row = blockIdx.x;
    float* x = X + (long long)row * cols;
    int tid = threadIdx.x;
    __shared__ float red[256];

    float m = -1e30f;
    for (int c = tid; c < cols; c += 256) m = fmaxf(m, x[c]);
    red[tid] = m; __syncthreads();
    for (int s = 128; s > 0; s >>= 1) {
        if (tid < s) red[tid] = fmaxf(red[tid], red[tid + s]);
        __syncthreads();
    }
    m = red[0]; __syncthreads();

    float sum = 0.f;
    for (int c = tid; c < cols; c += 256) {
        float e = __expf(x[c] - m);
        x[c] = e; sum += e;
    }
    red[tid] = sum; __syncthreads();
    for (int s = 128; s > 0; s >>= 1) {
        if (tid < s) red[tid] += red[tid + s];
        __syncthreads();
    }
    float inv = 1.0f / red[0];
    for (int c = tid; c < cols; c += 256) x[c] *= inv;
}

// ---------------------------------------------------------------------------
// Host-side driver
// ---------------------------------------------------------------------------
static inline void gemm(int tb,
                        const float* A, const float* B, float* C,
                        int M, int N, int K, int lda, int ldb, int ldc,
                        long long sAb, long long sAh,
                        long long sBb, long long sBh,
                        long long sCb, long long sCh,
                        int batch, int nh, float alpha,
                        float* rm_st = nullptr, float* sum_st = nullptr)
{
    dim3 g((N + TBN - 1) / TBN, (M + TBM - 1) / TBM, batch), b(256);
    if (tb) {
        if (rm_st)
            gemm_mma<true, true><<<g, b>>>(A, B, C, M, N, K, lda, ldb, ldc,
                                           sAb, sAh, sBb, sBh, sCb, sCh, nh, alpha,
                                           rm_st, sum_st);
        else
            gemm_mma<true, false><<<g, b>>>(A, B, C, M, N, K, lda, ldb, ldc,
                                            sAb, sAh, sBb, sBh, sCb, sCh, nh, alpha,
                                            nullptr, nullptr);
    } else {
        gemm_mma<false, false><<<g, b>>>(A, B, C, M, N, K, lda, ldb, ldc,
                                         sAb, sAh, sBb, sBh, sCb, sCh, nh, alpha,
                                         nullptr, nullptr);
    }
}

extern "C" void kernel_launch(void* const* d_in, const int* in_sizes, int n_in,
                              void* d_out, int out_size)
{
    const float* emb[4] = { (const float*)d_in[0], (const float*)d_in[1],
                            (const float*)d_in[2], (const float*)d_in[3] };
    const float* emb_C = (const float*)d_in[4];
    const float* Wq_c  = (const float*)d_in[5];
    const float* Wk_c  = (const float*)d_in[6];
    const float* Wv_c  = (const float*)d_in[7];
    const float* Wo_c  = (const float*)d_in[8];
    const float* Wq[4] = { (const float*)d_in[9],  (const float*)d_in[10],
                           (const float*)d_in[11], (const float*)d_in[12] };
    const float* Wk    = (const float*)d_in[13];
    const float* Wv    = (const float*)d_in[14];
    const float* Wo[4] = { (const float*)d_in[15], (const float*)d_in[16],
                           (const float*)d_in[17], (const float*)d_in[18] };
    float* out = (float*)d_out;

    float *q3, *k3, *v3, *sc, *oat, *that, *kvs, *Kb, *Vb, *attn, *ctxp;
    float *rowmax, *WkT, *WvT, *WqT;
    cudaGetSymbolAddress((void**)&q3,    g_q3);
    cudaGetSymbolAddress((void**)&k3,    g_k3);
    cudaGetSymbolAddress((void**)&v3,    g_v3);
    cudaGetSymbolAddress((void**)&sc,    g_sc);
    cudaGetSymbolAddress((void**)&oat,   g_oat);
    cudaGetSymbolAddress((void**)&that,  g_that);
    cudaGetSymbolAddress((void**)&kvs,   g_kvs);
    cudaGetSymbolAddress((void**)&Kb,    g_Kb);
    cudaGetSymbolAddress((void**)&Vb,    g_Vb);
    cudaGetSymbolAddress((void**)&attn,  g_attn);
    cudaGetSymbolAddress((void**)&ctxp,  g_ctx);
    cudaGetSymbolAddress((void**)&rowmax,g_rowmax);
    cudaGetSymbolAddress((void**)&WkT,   g_WkT);
    cudaGetSymbolAddress((void**)&WvT,   g_WvT);
    cudaGetSymbolAddress((void**)&WqT,   g_WqT);

    // ---------------- Weight pre-transposes + stats init ----------------
    {
        dim3 b(32, 8);
        dim3 g784((784 + 31) / 32, (784 + 31) / 32);
        transpose_kernel<<<g784, b>>>(Wk, WkT, 784, 784);
        transpose_kernel<<<g784, b>>>(Wv, WvT, 784, 784);
        dim3 g196((196 + 31) / 32, (196 + 31) / 32);
        for (int i = 0; i < 4; i++)
            transpose_kernel<<<g196, b>>>(Wq[i], WqT + (long long)i * 38416, 196, 196);
        stats_init_kernel<<<(512 * 196 + 255) / 256, 256>>>(rowmax, ctxp);
    }

    // ---------------- Stage A: SATAT over emb_C ----------------
    float* Wqkv = q3;                       // packed Wq_c|Wk_c|Wv_c
    float* qv   = attn;                     // q slab
    float* kvh  = attn + SZ_BNDC;           // k slab
    float* vv   = attn + 2 * SZ_BNDC;       // v slab
    pack4_kernel<<<dim3(4096, 3), 256>>>(Wq_c, Wk_c, Wv_c, Wv_c, Wqkv, 1048576LL);
    gemm(0, emb_C, Wqkv, qv, 6272, 1024, 1024, 1024, 1024, 1024,
         0, 0, 1048576, 0, SZ_BNDC, 0, 3, 1, 1.0f);

    gemm(1, qv, kvh, sc, 196, 196, 256, 1024, 1024, 196,
         200704, 256, 200704, 256, 153664, 38416, 128, 4, 0.0625f);
    softmax_kernel<<<25088, 256>>>(sc, 196);
    gemm(0, sc, vv, oat, 196, 256, 196, 196, 1024, 1024,
         153664, 38416, 200704, 256, 200704, 256, 128, 4, 1.0f);
    gemm(0, oat, Wo_c, that, 6272, 1024, 1024, 1024, 1024, 1024,
         0, 0, 0, 0, 0, 0, 1, 1, 1.0f);

    // ---------------- Stage B: KV token mix (fused K+V) ----------------
    kvs_kernel<<<(unsigned)((SZ_BNDC + 255) / 256), 256>>>(that, kvs);
    gemm(0, WkT, kvs, Kb, 784, 256, 784, 784, 256, 256,
         (long long)(WvT - WkT), 0, 0, 200704,
         (long long)(Vb - Kb), 200704, 64, 32, 1.0f);

    // ---------------- Stage C: 4 branches ----------------
    float* embP = q3;
    float* Qb4  = k3;
    float* WoP  = v3;
    float* ctx4 = oat;
    float* sums = ctxp;           // 1024 floats (512 z * 2)
    pack4_kernel<<<dim3((unsigned)((SZ_Q + 255) / 256), 4), 256>>>(
        emb[0], emb[1], emb[2], emb[3], embP, SZ_Q);
    pack4_kernel<<<dim3(256, 4), 256>>>(
        Wo[0], Wo[1], Wo[2], Wo[3], WoP, 65536);

    // Batched Q-mix: z = br*32 + b  (512 blocks, one launch)
    gemm(0, WqT, embP, Qb4, 196, 256, 196, 196, 256, 256,
         38416, 0, SZ_Q, 50176, SZ_Q, 50176, 128, 32, 1.0f);

    // QK (STATS instantiation) + fused softmax-PV per branch
    for (int br = 0; br < 4; br++) {
        const float* Qb = Qb4 + (long long)br * SZ_Q;
        float* rm_br  = rowmax + (long long)br * 128 * 196;
        float* sum_br = sums + (long long)br * 256;
        gemm(1, Qb, Kb, attn, 196, 784, 64, 256, 256, 784,
             50176, 64, 200704, 64, 614656, 153664, 128, 4, 1.0f,
             rm_br, sum_br);
        dim3 g(1, 2, 128), b(256);
        attn_pv_kernel<<<g, b>>>(attn, Vb, ctx4 + (long long)br * SZ_Q,
                                 rm_br, sum_br);
    }

    // Batched Wo: z = br  (392 blocks, one launch)
    gemm(0, ctx4, WoP, out, 6272, 256, 256, 256, 256, 256,
         SZ_Q, 0, 65536, 0, SZ_Q, 0, 4, 1, 1.0f);
}

// round 17
// speedup vs baseline: 1.1887x; 1.1664x over previous
#include <cuda_runtime.h>
#include <cuda_bf16.h>
#include <cstdint>

// ---------------------------------------------------------------------------
// Problem constants: B=32, N=196, DQ=256, DC=1024, H=4, DH=64, DHC=256, 4N=784
// ---------------------------------------------------------------------------

#define SZ_BNDC   6422528LL   // 32*196*1024  (also 32*784*256)
#define SZ_SC     4917248LL   // 32*4*196*196
#define SZ_Q      1605632LL   // 32*196*256
#define SZ_ATTN  19668992LL   // 32*4*196*784 (one branch)

// Scratch (device .bss, allocation-free) — same proven footprint.
__device__ float g_q3[SZ_BNDC];
__device__ float g_k3[SZ_BNDC];
__device__ float g_v3[SZ_BNDC];
__device__ float g_sc[SZ_SC];
__device__ float g_oat[SZ_BNDC];
__device__ float g_that[SZ_BNDC];
__device__ float g_kvs[SZ_BNDC];
__device__ float g_Kb[SZ_BNDC];
__device__ float g_Vb[SZ_BNDC];
__device__ float g_Qb[SZ_Q];
__device__ float g_attn[SZ_ATTN];
__device__ float g_ctx[SZ_Q];        // stats sum/sumsq accumulators (1024 used)
__device__ float g_gain[128];
__device__ float g_rowmax[512 * 196];
__device__ float g_WkT[614656];       // 784*784
__device__ float g_WvT[614656];
__device__ float g_WqT[4 * 38416];    // 4 * 196*196

// ---------------------------------------------------------------------------
// PTX helpers
// ---------------------------------------------------------------------------
__device__ __forceinline__ uint32_t smem_u32(const void* p) {
    return (uint32_t)__cvta_generic_to_shared(p);
}

__device__ __forceinline__ void ldsm_x4(uint32_t& r0, uint32_t& r1,
                                        uint32_t& r2, uint32_t& r3, uint32_t addr) {
    asm volatile("ldmatrix.sync.aligned.m8n8.x4.shared.b16 {%0,%1,%2,%3},[%4];"
                 : "=r"(r0), "=r"(r1), "=r"(r2), "=r"(r3) : "r"(addr));
}

__device__ __forceinline__ void ldsm_x4_t(uint32_t& r0, uint32_t& r1,
                                          uint32_t& r2, uint32_t& r3, uint32_t addr) {
    asm volatile("ldmatrix.sync.aligned.m8n8.x4.trans.shared.b16 {%0,%1,%2,%3},[%4];"
                 : "=r"(r0), "=r"(r1), "=r"(r2), "=r"(r3) : "r"(addr));
}

__device__ __forceinline__ void mma_bf16(float* c, const uint32_t* a, const uint32_t* b) {
    asm volatile("mma.sync.aligned.m16n8k16.row.col.f32.bf16.bf16.f32 "
                 "{%0,%1,%2,%3},{%4,%5,%6,%7},{%8,%9},{%0,%1,%2,%3};"
                 : "+f"(c[0]), "+f"(c[1]), "+f"(c[2]), "+f"(c[3])
                 : "r"(a[0]), "r"(a[1]), "r"(a[2]), "r"(a[3]),
                   "r"(b[0]), "r"(b[1]));
}

// Split-convert 4 consecutive fp32 into hi/lo bf16 planes with ONE 8-byte
// store per plane (addresses are 8B-aligned: row strides 24/136/72 bf16).
__device__ __forceinline__ void cvt_store4(__nv_bfloat16* hi, __nv_bfloat16* lo,
                                           float4 v) {
    __nv_bfloat16 h0 = __float2bfloat16(v.x), h1 = __float2bfloat16(v.y);
    __nv_bfloat16 h2 = __float2bfloat16(v.z), h3 = __float2bfloat16(v.w);
    __nv_bfloat162 hA = __halves2bfloat162(h0, h1);
    __nv_bfloat162 hB = __halves2bfloat162(h2, h3);
    uint2 hp; hp.x = *(uint32_t*)&hA; hp.y = *(uint32_t*)&hB;
    *(uint2*)hi = hp;
    __nv_bfloat162 lA = __halves2bfloat162(
        __float2bfloat16(v.x - __bfloat162float(h0)),
        __float2bfloat16(v.y - __bfloat162float(h1)));
    __nv_bfloat162 lB = __halves2bfloat162(
        __float2bfloat16(v.z - __bfloat162float(h2)),
        __float2bfloat16(v.w - __bfloat162float(h3)));
    uint2 lp; lp.x = *(uint32_t*)&lA; lp.y = *(uint32_t*)&lB;
    *(uint2*)lo = lp;
}

// ---------------------------------------------------------------------------
// Tile geometry: 128x128 block tile, TBK=16, double-buffered STATIC smem.
// ---------------------------------------------------------------------------
#define TBM 128
#define TBN 128
#define TBK 16
#define A_STRIDE 24                 // TBK + 8 pad
#define B_STRIDE 136                // TBN + 8 pad
#define PVB_STRIDE 72               // 64 + 8 pad

// ---------------------------------------------------------------------------
// Tensor-core batched GEMM, split-bf16 (3 MMA) fp32 emulation.
// STATS (compile-time, QK instantiation only): fold sum/sumsq of the masked
// outputs into the epilogue store loop (2 live floats; NO rowmax, NO
// occupancy clamp — launch bounds identical to the round-12 kernel).
// ---------------------------------------------------------------------------
template<bool TB, bool STATS>
__global__ __launch_bounds__(256)
void gemm_mma(const float* __restrict__ A, const float* __restrict__ B,
              float* __restrict__ C,
              int M, int N, int K, int lda, int ldb, int ldc,
              long long sAb, long long sAh, long long sBb, long long sBh,
              long long sCb, long long sCh, int nh, float alpha,
              float* sum_st)
{
    int z  = blockIdx.z;
    int bb = z / nh, hh = z % nh;
    A += bb * sAb + hh * sAh;
    B += bb * sBb + hh * sBh;
    C += bb * sCb + hh * sCh;

    __shared__ __align__(16) __nv_bfloat16 As[2][2][TBM][A_STRIDE];  // 24.0 KB
    __shared__ __align__(16) __nv_bfloat16 Bs[2][2][TBK][B_STRIDE];  // 17.0 KB

    const int tid  = threadIdx.x;
    const int lane = tid & 31;
    const int wid  = tid >> 5;
    const int wm   = wid >> 2;
    const int wn   = wid & 3;
    const int m0 = blockIdx.y * TBM, n0 = blockIdx.x * TBN;

    float acc[4][4][4];
#pragma unroll
    for (int i = 0; i < 4; i++)
#pragma unroll
        for (int j = 0; j < 4; j++)
#pragma unroll
            for (int r = 0; r < 4; r++) acc[i][j][r] = 0.f;

    const int ar  = tid >> 2, ac4 = tid & 3;    // A: 64 rows/pass, 4 f4/row
    const int bkr = tid >> 5, bc4 = tid & 31;   // B NN: 8 k-rows/pass, 32 f4/row
    const int bnr = tid >> 2, bk4 = tid & 3;    // B NT: 64 n-rows/pass, 4 f4/row

    float4 aPre[2], bPre[2];

#define LOAD_REGS(K0)                                                           \
    {                                                                           \
        int k0_ = (K0);                                                         \
        _Pragma("unroll")                                                       \
        for (int i = 0; i < 2; i++) {                                           \
            int gm = m0 + ar + i * 64, gk = k0_ + ac4 * 4;                      \
            aPre[i] = (gm < M && gk < K)                                        \
                ? *(const float4*)&A[(long long)gm * lda + gk]                  \
                : make_float4(0.f, 0.f, 0.f, 0.f);                              \
        }                                                                       \
        if (!TB) {                                                              \
            _Pragma("unroll")                                                   \
            for (int i = 0; i < 2; i++) {                                       \
                int gk = k0_ + bkr + i * 8, gn = n0 + bc4 * 4;                  \
                bPre[i] = (gk < K && gn < N)                                    \
                    ? *(const float4*)&B[(long long)gk * ldb + gn]              \
                    : make_float4(0.f, 0.f, 0.f, 0.f);                          \
            }                                                                   \
        } else {                                                                \
            _Pragma("unroll")                                                   \
            for (int i = 0; i < 2; i++) {                                       \
                int gn = n0 + bnr + i * 64, gk = k0_ + bk4 * 4;                 \
                bPre[i] = (gn < N && gk < K)                                    \
                    ? *(const float4*)&B[(long long)gn * ldb + gk]              \
                    : make_float4(0.f, 0.f, 0.f, 0.f);                          \
            }                                                                   \
        }                                                                       \
    }

#define CVT_B_SC(s, dr, dc, f)                                                  \
    {                                                                           \
        __nv_bfloat16 hi_ = __float2bfloat16(f);                                \
        Bs[s][0][dr][dc] = hi_;                                                 \
        Bs[s][1][dr][dc] = __float2bfloat16((f) - __bfloat162float(hi_));       \
    }

#define STORE_SMEM(s)                                                           \
    {                                                                           \
        _Pragma("unroll")                                                       \
        for (int i = 0; i < 2; i++) {                                           \
            int m = ar + i * 64, c = ac4 * 4;                                   \
            cvt_store4(&As[s][0][m][c], &As[s][1][m][c], aPre[i]);              \
        }                                                                       \
        if (!TB) {                                                              \
            _Pragma("unroll")                                                   \
            for (int i = 0; i < 2; i++) {                                       \
                int k = bkr + i * 8, c = bc4 * 4;                               \
                cvt_store4(&Bs[s][0][k][c], &Bs[s][1][k][c], bPre[i]);          \
            }                                                                   \
        } else {                                                                \
            _Pragma("unroll")                                                   \
            for (int i = 0; i < 2; i++) {                                       \
                int n = bnr + i * 64, k = bk4 * 4;                              \
                CVT_B_SC(s, k + 0, n, bPre[i].x); CVT_B_SC(s, k + 1, n, bPre[i].y); \
                CVT_B_SC(s, k + 2, n, bPre[i].z); CVT_B_SC(s, k + 3, n, bPre[i].w); \
            }                                                                   \
        }                                                                       \
    }

#define COMPUTE(s)                                                              \
    {                                                                           \
        uint32_t Ah[4][4], Al[4][4], Bh[4][2], Bl[4][2];                        \
        _Pragma("unroll")                                                       \
        for (int i = 0; i < 4; i++) {                                           \
            int row = wm * 64 + i * 16 + (lane & 15);                           \
            int col = (lane >> 4) << 3;                                         \
            ldsm_x4(Ah[i][0], Ah[i][1], Ah[i][2], Ah[i][3],                     \
                    smem_u32(&As[s][0][row][col]));                             \
            ldsm_x4(Al[i][0], Al[i][1], Al[i][2], Al[i][3],                     \
                    smem_u32(&As[s][1][row][col]));                             \
        }                                                                       \
        _Pragma("unroll")                                                       \
        for (int t2 = 0; t2 < 2; t2++) {                                        \
            int row = lane & 15;                                                \
            int col = wn * 32 + t2 * 16 + ((lane >> 4) << 3);                   \
            uint32_t r0, r1, r2, r3;                                            \
            ldsm_x4_t(r0, r1, r2, r3, smem_u32(&Bs[s][0][row][col]));           \
            Bh[t2*2][0] = r0; Bh[t2*2][1] = r1;                                 \
            Bh[t2*2+1][0] = r2; Bh[t2*2+1][1] = r3;                             \
            ldsm_x4_t(r0, r1, r2, r3, smem_u32(&Bs[s][1][row][col]));           \
            Bl[t2*2][0] = r0; Bl[t2*2][1] = r1;                                 \
            Bl[t2*2+1][0] = r2; Bl[t2*2+1][1] = r3;                             \
        }                                                                       \
        _Pragma("unroll")                                                       \
        for (int i = 0; i < 4; i++)                                             \
            _Pragma("unroll")                                                   \
            for (int j = 0; j < 4; j++) {                                       \
                mma_bf16(acc[i][j], Ah[i], Bh[j]);                              \
                mma_bf16(acc[i][j], Ah[i], Bl[j]);                              \
                mma_bf16(acc[i][j], Al[i], Bh[j]);                              \
            }                                                                   \
    }

    const int ktiles = (K + TBK - 1) / TBK;

    LOAD_REGS(0);
    STORE_SMEM(0);
    __syncthreads();

    for (int t = 0; t < ktiles; t++) {
        const int cur = t & 1;
        bool last = (t == ktiles - 1);
        if (!last) LOAD_REGS((t + 1) * TBK);
        COMPUTE(cur);
        if (!last) {
            STORE_SMEM(cur ^ 1);      // other stage: prior sync drained its readers
            __syncthreads();
        }
    }

    const int g  = lane >> 2;
    const int tg = lane & 3;
    float ls = 0.f, ls2 = 0.f;        // dead unless STATS
#pragma unroll
    for (int i = 0; i < 4; i++) {
        int r0w = m0 + wm * 64 + i * 16 + g;
        int r1w = r0w + 8;
#pragma unroll
        for (int j = 0; j < 4; j++) {
            int c0 = n0 + wn * 32 + j * 8 + tg * 2;
            if (c0 < N) {
                if (r0w < M) {
                    float2 v = make_float2(alpha * acc[i][j][0], alpha * acc[i][j][1]);
                    if (STATS) {
                        ls += v.x; ls2 += v.x * v.x;
                        if (c0 + 1 < N) { ls += v.y; ls2 += v.y * v.y; }
                    }
                    *(float2*)&C[(long long)r0w * ldc + c0] = v;
                }
                if (r1w < M) {
                    float2 v = make_float2(alpha * acc[i][j][2], alpha * acc[i][j][3]);
                    if (STATS) {
                        ls += v.x; ls2 += v.x * v.x;
                        if (c0 + 1 < N) { ls += v.y; ls2 += v.y * v.y; }
                    }
                    *(float2*)&C[(long long)r1w * ldc + c0] = v;
                }
            }
        }
    }

    if (STATS) {
#pragma unroll
        for (int o = 16; o; o >>= 1) {
            ls  += __shfl_xor_sync(~0u, ls,  o);
            ls2 += __shfl_xor_sync(~0u, ls2, o);
        }
        if (lane == 0) {
            atomicAdd(&sum_st[z * 2 + 0], ls);
            atomicAdd(&sum_st[z * 2 + 1], ls2);
        }
    }
#undef LOAD_REGS
#undef STORE_SMEM
#undef COMPUTE
#undef CVT_B_SC
}

// ---------------------------------------------------------------------------
// Fused exp-softmax + P@V GEMM (one branch).  M=196, N=64, K=784 per z (128).
// gain/mean computed inline from fused-stats sums; no rowmax needed:
// instance-normed logits are O(5) sigma, exp(g*(x-mean)) <= ~e^6 (safe fp32).
// ---------------------------------------------------------------------------
__global__ __launch_bounds__(256)
void attn_pv_kernel(const float* __restrict__ attn, const float* __restrict__ V,
                    float* __restrict__ ctx, const float* __restrict__ sums)
{
    const int Mv = 196, Kv = 784;
    int z = blockIdx.z;               // 0..127 = b*4+h
    int bb = z >> 2, hh = z & 3;
    const float* A = attn + (long long)bb * 614656 + (long long)hh * 153664;
    const float* B = V    + (long long)bb * 200704 + hh * 64;
    float*       C = ctx  + (long long)bb * 50176  + hh * 64;
    float s  = sums[z * 2 + 0];
    float s2 = sums[z * 2 + 1];
    float mean = s / 153664.f;
    const float gv = rsqrtf(s2 / 153664.f - mean * mean + 1e-5f);
    const float gm = gv * mean;       // exponent offset (softmax shift-invariant)

    __shared__ __align__(16) __nv_bfloat16 As[2][2][128][A_STRIDE];    // 24 KB
    __shared__ __align__(16) __nv_bfloat16 Bs[2][2][TBK][PVB_STRIDE];  // 9 KB
    __shared__ float sden[128];

    const int tid  = threadIdx.x;
    const int lane = tid & 31;
    const int wid  = tid >> 5;
    const int wm   = wid >> 1;   // 0..3 : 32 rows each
    const int wn   = wid & 1;    // 0..1 : 32 cols each
    const int m0 = blockIdx.y * 128;

    if (tid < 128) sden[tid] = 0.f;

    float acc[2][4][4];
#pragma unroll
    for (int i = 0; i < 2; i++)
#pragma unroll
        for (int j = 0; j < 4; j++)
#pragma unroll
            for (int r = 0; r < 4; r++) acc[i][j][r] = 0.f;

    const int ar  = tid >> 2, ac4 = tid & 3;   // A: 64 rows/pass, 4 f4/row
    const int brr = tid >> 4, bc4 = tid & 15;  // B: 16 rows, 16 f4/row, 1 pass

    float4 aPre[2], bPre;
    int k0s = 0;

#define PV_LOAD(K0)                                                             \
    {                                                                           \
        int k0_ = (K0);                                                         \
        _Pragma("unroll")                                                       \
        for (int i = 0; i < 2; i++) {                                           \
            int gm_ = m0 + ar + i * 64, gk = k0_ + ac4 * 4;                     \
            aPre[i] = (gm_ < Mv && gk < Kv)                                     \
                ? *(const float4*)&A[(long long)gm_ * 784 + gk]                 \
                : make_float4(0.f, 0.f, 0.f, 0.f);                              \
        }                                                                       \
        {                                                                       \
            int gk = k0_ + brr;                                                 \
            bPre = (gk < Kv)                                                    \
                ? *(const float4*)&B[(long long)gk * 256 + bc4 * 4]             \
                : make_float4(0.f, 0.f, 0.f, 0.f);                              \
        }                                                                       \
        k0s = k0_;                                                              \
    }

#define PV_STORE(s)                                                             \
    {                                                                           \
        _Pragma("unroll")                                                       \
        for (int i = 0; i < 2; i++) {                                           \
            int m = ar + i * 64, gm_ = m0 + m;                                  \
            bool rok = (gm_ < Mv);                                              \
            float4 e4;                                                          \
            float vv[4] = { aPre[i].x, aPre[i].y, aPre[i].z, aPre[i].w };       \
            float ee[4];                                                        \
            _Pragma("unroll")                                                   \
            for (int cc = 0; cc < 4; cc++) {                                    \
                int gk = k0s + ac4 * 4 + cc;                                    \
                ee[cc] = (rok && gk < Kv) ? __expf(gv * vv[cc] - gm) : 0.f;     \
            }                                                                   \
            e4 = make_float4(ee[0], ee[1], ee[2], ee[3]);                       \
            float part = ee[0] + ee[1] + ee[2] + ee[3];                         \
            cvt_store4(&As[s][0][m][ac4 * 4], &As[s][1][m][ac4 * 4], e4);       \
            if (part != 0.f) atomicAdd(&sden[m], part);                         \
        }                                                                       \
        {                                                                       \
            int k = brr, c = bc4 * 4;                                           \
            cvt_store4(&Bs[s][0][k][c], &Bs[s][1][k][c], bPre);                 \
        }                                                                       \
    }

    const int ktiles = (Kv + TBK - 1) / TBK;   // 49

    PV_LOAD(0);
    __syncthreads();           // sden init visible before first atomicAdd
    PV_STORE(0);
    __syncthreads();

    for (int t = 0; t < ktiles; t++) {
        const int cur = t & 1;
        bool last = (t == ktiles - 1);
        if (!last) PV_LOAD((t + 1) * TBK);
        {
            uint32_t Ah[2][4], Al[2][4], Bh[4][2], Bl[4][2];
#pragma unroll
            for (int i = 0; i < 2; i++) {
                int row = wm * 32 + i * 16 + (lane & 15);
                int col = (lane >> 4) << 3;
                ldsm_x4(Ah[i][0], Ah[i][1], Ah[i][2], Ah[i][3],
                        smem_u32(&As[cur][0][row][col]));
                ldsm_x4(Al[i][0], Al[i][1], Al[i][2], Al[i][3],
                        smem_u32(&As[cur][1][row][col]));
            }
            {
                int row = lane & 15;
                int col = wn * 32 + ((lane >> 4) << 3);
                uint32_t r0, r1, r2, r3;
                ldsm_x4_t(r0, r1, r2, r3, smem_u32(&Bs[cur][0][row][col]));
                Bh[0][0] = r0; Bh[0][1] = r1; Bh[1][0] = r2; Bh[1][1] = r3;
                ldsm_x4_t(r0, r1, r2, r3, smem_u32(&Bs[cur][0][row][col + 16]));
                Bh[2][0] = r0; Bh[2][1] = r1; Bh[3][0] = r2; Bh[3][1] = r3;
                ldsm_x4_t(r0, r1, r2, r3, smem_u32(&Bs[cur][1][row][col]));
                Bl[0][0] = r0; Bl[0][1] = r1; Bl[1][0] = r2; Bl[1][1] = r3;
                ldsm_x4_t(r0, r1, r2, r3, smem_u32(&Bs[cur][1][row][col + 16]));
                Bl[2][0] = r0; Bl[2][1] = r1; Bl[3][0] = r2; Bl[3][1] = r3;
            }
#pragma unroll
            for (int i = 0; i < 2; i++)
#pragma unroll
                for (int j = 0; j < 4; j++) {
                    mma_bf16(acc[i][j], Ah[i], Bh[j]);
                    mma_bf16(acc[i][j], Ah[i], Bl[j]);
                    mma_bf16(acc[i][j], Al[i], Bh[j]);
                }
        }
        if (!last) {
            PV_STORE(cur ^ 1);
            __syncthreads();
        }
    }

    const int g  = lane >> 2;
    const int tg = lane & 3;
#pragma unroll
    for (int i = 0; i < 2; i++) {
        int lr0 = wm * 32 + i * 16 + g;
        int lr1 = lr0 + 8;
        int r0w = m0 + lr0, r1w = m0 + lr1;
        float d0 = (r0w < Mv) ? 1.0f / sden[lr0] : 0.f;
        float d1 = (r1w < Mv) ? 1.0f / sden[lr1] : 0.f;
#pragma unroll
        for (int j = 0; j < 4; j++) {
            int c0 = wn * 32 + j * 8 + tg * 2;
            if (r0w < Mv) {
                float2 v = make_float2(acc[i][j][0] * d0, acc[i][j][1] * d0);
                *(float2*)&C[(long long)r0w * 256 + c0] = v;
            }
            if (r1w < Mv) {
                float2 v = make_float2(acc[i][j][2] * d1, acc[i][j][3] * d1);
                *(float2*)&C[(long long)r1w * 256 + c0] = v;
            }
        }
    }
#undef PV_LOAD
#undef PV_STORE
}

// ---------------------------------------------------------------------------
// Small helpers
// ---------------------------------------------------------------------------
__global__ void transpose_kernel(const float* __restrict__ src, float* __restrict__ dst,
                                 int M, int N)
{
    __shared__ float t[32][33];
    int x = blockIdx.x * 32 + threadIdx.x;
    int y0 = blockIdx.y * 32 + threadIdx.y;
#pragma unroll
    for (int i = 0; i < 32; i += 8) {
        int y = y0 + i;
        t[threadIdx.y + i][threadIdx.x] = (y < M && x < N) ? src[(long long)y * N + x] : 0.f;
    }
    __syncthreads();
    int xo = blockIdx.y * 32 + threadIdx.x;
    int yo0 = blockIdx.x * 32 + threadIdx.y;
#pragma unroll
    for (int i = 0; i < 32; i += 8) {
        int yo = yo0 + i;
        if (yo < N && xo < M) dst[(long long)yo * M + xo] = t[threadIdx.x][threadIdx.y + i];
    }
}

// Pack up to 4 separate buffers into one contiguous [grid.y][n] buffer.
__global__ void pack4_kernel(const float* __restrict__ p0, const float* __restrict__ p1,
                             const float* __restrict__ p2, const float* __restrict__ p3,
                             float* __restrict__ dst, long long n)
{
    long long i = (long long)blockIdx.x * 256 + threadIdx.x;
    int br = blockIdx.y;
    if (i < n) {
        const float* src = (br == 0) ? p0 : (br == 1) ? p1 : (br == 2) ? p2 : p3;
        dst[(long long)br * n + i] = src[i];
    }
}

// Reset fused-stats accumulators (1024 floats).
__global__ void stats_init_kernel(float* __restrict__ sums)
{
    int i = blockIdx.x * 256 + threadIdx.x;
    if (i < 1024) sums[i] = 0.f;
}

// KV_S[b, j*196+t, c] = T_hat[b, t, j*256 + c]
__global__ void kvs_kernel(const float* __restrict__ T, float* __restrict__ KVS)
{
    long long i = (long long)blockIdx.x * blockDim.x + threadIdx.x;
    if (i >= SZ_BNDC) return;
    int c = (int)(i & 255);
    long long t2 = i >> 8;
    int n = (int)(t2 % 784);
    int b = (int)(t2 / 784);
    int j = n / 196, t = n % 196;
    KVS[i] = T[((long long)b * 196 + t) * 1024 + (long long)j * 256 + c];
}

// Plain row softmax (SATAT scores, 196 cols)
__global__ void softmax_kernel(float* __restrict__ X, int cols)
{
    int row = blockIdx.x;
    float* x = X + (long long)row * cols;
    int tid = threadIdx.x;
    __shared__ float red[256];

    float m = -1e30f;
    for (int c = tid; c < cols; c += 256) m = fmaxf(m, x[c]);
    red[tid] = m; __syncthreads();
    for (int s = 128; s > 0; s >>= 1) {
        if (tid < s) red[tid] = fmaxf(red[tid], red[tid + s]);
        __syncthreads();
    }
    m = red[0]; __syncthreads();

    float sum = 0.f;
    for (int c = tid; c < cols; c += 256) {
        float e = __expf(x[c] - m);
        x[c] = e; sum += e;
    }
    red[tid] = sum; __syncthreads();
    for (int s = 128; s > 0; s >>= 1) {
        if (tid < s) red[tid] += red[tid + s];
        __syncthreads();
    }
    float inv = 1.0f / red[0];
    for (int c = tid; c < cols; c += 256) x[c] *= inv;
}

// ---------------------------------------------------------------------------
// Host-side driver
// ---------------------------------------------------------------------------
static inline void gemm(int tb,
                        const float* A, const float* B, float* C,
                        int M, int N, int K, int lda, int ldb, int ldc,
                        long long sAb, long long sAh,
                        long long sBb, long long sBh,
                        long long sCb, long long sCh,
                        int batch, int nh, float alpha,
                        float* sum_st = nullptr)
{
    dim3 g((N + TBN - 1) / TBN, (M + TBM - 1) / TBM, batch), b(256);
    if (tb) {
        if (sum_st)
            gemm_mma<true, true><<<g, b>>>(A, B, C, M, N, K, lda, ldb, ldc,
                                           sAb, sAh, sBb, sBh, sCb, sCh, nh, alpha,
                                           sum_st);
        else
            gemm_mma<true, false><<<g, b>>>(A, B, C, M, N, K, lda, ldb, ldc,
                                            sAb, sAh, sBb, sBh, sCb, sCh, nh, alpha,
                                            nullptr);
    } else {
        gemm_mma<false, false><<<g, b>>>(A, B, C, M, N, K, lda, ldb, ldc,
                                         sAb, sAh, sBb, sBh, sCb, sCh, nh, alpha,
                                         nullptr);
    }
}

extern "C" void kernel_launch(void* const* d_in, const int* in_sizes, int n_in,
                              void* d_out, int out_size)
{
    const float* emb[4] = { (const float*)d_in[0], (const float*)d_in[1],
                            (const float*)d_in[2], (const float*)d_in[3] };
    const float* emb_C = (const float*)d_in[4];
    const float* Wq_c  = (const float*)d_in[5];
    const float* Wk_c  = (const float*)d_in[6];
    const float* Wv_c  = (const float*)d_in[7];
    const float* Wo_c  = (const float*)d_in[8];
    const float* Wq[4] = { (const float*)d_in[9],  (const float*)d_in[10],
                           (const float*)d_in[11], (const float*)d_in[12] };
    const float* Wk    = (const float*)d_in[13];
    const float* Wv    = (const float*)d_in[14];
    const float* Wo[4] = { (const float*)d_in[15], (const float*)d_in[16],
                           (const float*)d_in[17], (const float*)d_in[18] };
    float* out = (float*)d_out;

    float *q3, *k3, *v3, *sc, *oat, *that, *kvs, *Kb, *Vb, *attn, *ctxp;
    float *WkT, *WvT, *WqT;
    cudaGetSymbolAddress((void**)&q3,    g_q3);
    cudaGetSymbolAddress((void**)&k3,    g_k3);
    cudaGetSymbolAddress((void**)&v3,    g_v3);
    cudaGetSymbolAddress((void**)&sc,    g_sc);
    cudaGetSymbolAddress((void**)&oat,   g_oat);
    cudaGetSymbolAddress((void**)&that,  g_that);
    cudaGetSymbolAddress((void**)&kvs,   g_kvs);
    cudaGetSymbolAddress((void**)&Kb,    g_Kb);
    cudaGetSymbolAddress((void**)&Vb,    g_Vb);
    cudaGetSymbolAddress((void**)&attn,  g_attn);
    cudaGetSymbolAddress((void**)&ctxp,  g_ctx);
    cudaGetSymbolAddress((void**)&WkT,   g_WkT);
    cudaGetSymbolAddress((void**)&WvT,   g_WvT);
    cudaGetSymbolAddress((void**)&WqT,   g_WqT);

    // ---------------- Weight pre-transposes + stats init ----------------
    {
        dim3 b(32, 8);
        dim3 g784((784 + 31) / 32, (784 + 31) / 32);
        transpose_kernel<<<g784, b>>>(Wk, WkT, 784, 784);
        transpose_kernel<<<g784, b>>>(Wv, WvT, 784, 784);
        dim3 g196((196 + 31) / 32, (196 + 31) / 32);
        for (int i = 0; i < 4; i++)
            transpose_kernel<<<g196, b>>>(Wq[i], WqT + (long long)i * 38416, 196, 196);
        stats_init_kernel<<<4, 256>>>(ctxp);
    }

    // ---------------- Stage A: SATAT over emb_C ----------------
    float* Wqkv = q3;                       // packed Wq_c|Wk_c|Wv_c
    float* qv   = attn;                     // q slab
    float* kvh  = attn + SZ_BNDC;           // k slab
    float* vv   = attn + 2 * SZ_BNDC;       // v slab
    pack4_kernel<<<dim3(4096, 3), 256>>>(Wq_c, Wk_c, Wv_c, Wv_c, Wqkv, 1048576LL);
    gemm(0, emb_C, Wqkv, qv, 6272, 1024, 1024, 1024, 1024, 1024,
         0, 0, 1048576, 0, SZ_BNDC, 0, 3, 1, 1.0f);

    gemm(1, qv, kvh, sc, 196, 196, 256, 1024, 1024, 196,
         200704, 256, 200704, 256, 153664, 38416, 128, 4, 0.0625f);
    softmax_kernel<<<25088, 256>>>(sc, 196);
    gemm(0, sc, vv, oat, 196, 256, 196, 196, 1024, 1024,
         153664, 38416, 200704, 256, 200704, 256, 128, 4, 1.0f);
    gemm(0, oat, Wo_c, that, 6272, 1024, 1024, 1024, 1024, 1024,
         0, 0, 0, 0, 0, 0, 1, 1, 1.0f);

    // ---------------- Stage B: KV token mix (fused K+V) ----------------
    kvs_kernel<<<(unsigned)((SZ_BNDC + 255) / 256), 256>>>(that, kvs);
    gemm(0, WkT, kvs, Kb, 784, 256, 784, 784, 256, 256,
         (long long)(WvT - WkT), 0, 0, 200704,
         (long long)(Vb - Kb), 200704, 64, 32, 1.0f);

    // ---------------- Stage C: 4 branches ----------------
    float* embP = q3;
    float* Qb4  = k3;
    float* WoP  = v3;
    float* ctx4 = oat;
    float* sums = ctxp;           // 1024 floats (512 z * 2)
    pack4_kernel<<<dim3((unsigned)((SZ_Q + 255) / 256), 4), 256>>>(
        emb[0], emb[1], emb[2], emb[3], embP, SZ_Q);
    pack4_kernel<<<dim3(256, 4), 256>>>(
        Wo[0], Wo[1], Wo[2], Wo[3], WoP, 65536);

    // Batched Q-mix: z = br*32 + b  (512 blocks, one launch)
    gemm(0, WqT, embP, Qb4, 196, 256, 196, 196, 256, 256,
         38416, 0, SZ_Q, 50176, SZ_Q, 50176, 128, 32, 1.0f);

    // QK (sum/sumsq fused into epilogue) + fused softmax-PV per branch
    for (int br = 0; br < 4; br++) {
        const float* Qb = Qb4 + (long long)br * SZ_Q;
        float* sum_br = sums + (long long)br * 256;
        gemm(1, Qb, Kb, attn, 196, 784, 64, 256, 256, 784,
             50176, 64, 200704, 64, 614656, 153664, 128, 4, 1.0f,
             sum_br);
        dim3 g(1, 2, 128), b(256);
        attn_pv_kernel<<<g, b>>>(attn, Vb, ctx4 + (long long)br * SZ_Q,
                                 sum_br);
    }

    // Batched Wo: z = br  (392 blocks, one launch)
    gemm(0, ctx4, WoP, out, 6272, 256, 256, 256, 256, 256,
         SZ_Q, 0, 65536, 0, SZ_Q, 0, 4, 1, 1.0f);
}